// round 11
// baseline (speedup 1.0000x reference)
#include <cuda_runtime.h>
#include <cuda_bf16.h>
#include <math.h>
#include <stdint.h>

// ---------------- problem constants ----------------
#define BB   2
#define SS   336
#define VV   8
#define DD   256
#define HH   8
#define DK   32
#define PP   96
#define NT   (BB*VV*SS)      // 5376 tokens
#define SD   (SS*DD)         // 86016
#define RSQRT_DK 0.17677669529663687f   // 1/sqrt(32)

// ---------------- scratch ----------------
__device__ float g_E[NT*DD];
__device__ float g_Q[NT*DD];
__device__ float g_K[NT*DD];
__device__ float g_V[NT*DD];
__device__ float g_O[NT*DD];
// transposed bf16 weight images W^T[n][k], hi/lo split: [w(4)][256][256]
__device__ __align__(16) __nv_bfloat16 g_WtH[4*65536];
__device__ __align__(16) __nv_bfloat16 g_WtL[4*65536];
// phase-A QKV bf16 images: [(g*8+h)*336 + s]*32 + d  (Q pre-scaled by 1/sqrt(dk))
#define IMG_ELEMS (128*336*32)
__device__ __align__(16) __nv_bfloat16 g_iQH[IMG_ELEMS], g_iQL[IMG_ELEMS];
__device__ __align__(16) __nv_bfloat16 g_iKH[IMG_ELEMS], g_iKL[IMG_ELEMS];
__device__ __align__(16) __nv_bfloat16 g_iVH[IMG_ELEMS], g_iVL[IMG_ELEMS];

// ---------------- helpers ----------------
__device__ __forceinline__ uint32_t smem_u32(const void* p) {
    uint32_t a;
    asm("{ .reg .u64 t; cvta.to.shared.u64 t, %1; cvt.u32.u64 %0, t; }" : "=r"(a) : "l"(p));
    return a;
}
__device__ __forceinline__ void ldsm4(uint32_t& r0, uint32_t& r1, uint32_t& r2, uint32_t& r3,
                                      uint32_t a) {
    asm volatile("ldmatrix.sync.aligned.m8n8.x4.shared.b16 {%0,%1,%2,%3}, [%4];"
        : "=r"(r0), "=r"(r1), "=r"(r2), "=r"(r3) : "r"(a));
}
__device__ __forceinline__ void mma16816(float* c, const uint32_t* a, const uint32_t* b) {
    asm volatile("mma.sync.aligned.m16n8k16.row.col.f32.bf16.bf16.f32 "
        "{%0,%1,%2,%3}, {%4,%5,%6,%7}, {%8,%9}, {%0,%1,%2,%3};"
        : "+f"(c[0]), "+f"(c[1]), "+f"(c[2]), "+f"(c[3])
        : "r"(a[0]), "r"(a[1]), "r"(a[2]), "r"(a[3]), "r"(b[0]), "r"(b[1]));
}
__device__ __forceinline__ void cpa16(uint32_t dst, const void* src) {
    asm volatile("cp.async.cg.shared.global [%0], [%1], 16;" :: "r"(dst), "l"(src));
}
#define CPA_COMMIT() asm volatile("cp.async.commit_group;" ::: "memory")
#define CPA_WAIT0()  asm volatile("cp.async.wait_group 0;" ::: "memory")

__device__ __forceinline__ uint32_t pk_bf2(float lo, float hi) {
    __nv_bfloat162 h = __floats2bfloat162_rn(lo, hi);
    return *(uint32_t*)&h;
}

// ---------------- embed ----------------
__global__ void k_embed(const float* __restrict__ x,
                        const float* __restrict__ ew,
                        const float* __restrict__ eb) {
    int idx = blockIdx.x * 256 + threadIdx.x;
    int d = idx & 255;
    int t = idx >> 8;
    int b = t / (VV*SS);
    int r = t - b*(VV*SS);
    int v = r / SS;
    int s = r - v*SS;
    g_E[idx] = x[(b*SS + s)*VV + v] * ew[d] + eb[d];
}

// ---------------- weight prep: W^T + bf16 hi/lo split ----------------
__global__ void k_prep(const float* __restrict__ Wq, const float* __restrict__ Wk,
                       const float* __restrict__ Wv, const float* __restrict__ Wo) {
    int e = blockIdx.x * 256 + threadIdx.x;   // 0..65535
    int w = blockIdx.y;
    int n = e >> 8, k = e & 255;
    const float* W = (w == 0) ? Wq : (w == 1) ? Wk : (w == 2) ? Wv : Wo;
    float a = W[k*256 + n];
    __nv_bfloat16 h = __float2bfloat16(a);
    __nv_bfloat16 l = __float2bfloat16(a - __bfloat162float(h));
    g_WtH[w*65536 + n*256 + k] = h;
    g_WtL[w*65536 + n*256 + k] = l;
}

// ---------------- pipelined mma.sync bf16x3 QKV GEMM ----------------
// CTA tile 64x256, 8 warps (warp tile 32x64), K-chunks of 64, double-buffered + cp.async.
#define GA(buf)  ((buf)*18432)                        // A hi @+0, lo @+9216
#define GBH(buf) (36864 + (buf)*73728)
#define GBL(buf) (36864 + (buf)*73728 + 36864)
#define SMEM_GEMM 184320

__device__ __forceinline__ void tgemm_body(char* sm, const float* __restrict__ A,
                                           const __nv_bfloat16* __restrict__ WtH,
                                           const __nv_bfloat16* __restrict__ WtL,
                                           const float* __restrict__ bias,
                                           float* __restrict__ C,
                                           int mode, int y) {
    const int tid = threadIdx.x;
    const int wid = tid >> 5, lane = tid & 31;
    const int m0 = blockIdx.x * 64;
    const int wm = (wid & 1) * 32;
    const int wn = (wid >> 1) * 64;
    uint32_t sb = smem_u32(sm);

    float acc[2][8][4];
#pragma unroll
    for (int i = 0; i < 2; i++)
#pragma unroll
        for (int j = 0; j < 8; j++)
#pragma unroll
            for (int q = 0; q < 4; q++) acc[i][j][q] = 0.f;

    uint32_t aRow = wm + (lane & 7) + ((lane >> 3) & 1) * 8;
    uint32_t aOff = aRow*144 + ((lane >> 4) & 1)*16;
    uint32_t bRow = wn + (lane & 7) + ((lane >> 4) & 1) * 8;
    uint32_t bOff = bRow*144 + ((lane >> 3) & 1)*16;

    // prologue: A chunk0 -> regs, B chunk0 -> cp.async buf0
    float4 av[4];
    {
        const float4* Ag = (const float4*)(A + m0*256);
#pragma unroll
        for (int i = 0; i < 4; i++) {
            int f = tid + 256*i;
            av[i] = Ag[(f >> 4)*64 + (f & 15)];
        }
#pragma unroll
        for (int i = 0; i < 8; i++) {
            int f = tid + 256*i;
            int r = f >> 3, q = f & 7;
            uint32_t off = (uint32_t)r*144 + (uint32_t)q*16;
            cpa16(sb + GBH(0) + off, WtH + (r << 8) + q*8);
            cpa16(sb + GBL(0) + off, WtL + (r << 8) + q*8);
        }
        CPA_COMMIT();
    }

#pragma unroll
    for (int kc = 0; kc < 4; kc++) {
        int buf = kc & 1;
#pragma unroll
        for (int i = 0; i < 4; i++) {
            int f = tid + 256*i;
            int r = f >> 4, q = f & 15;
            float4 v = av[i];
            __nv_bfloat16 h0 = __float2bfloat16(v.x);
            __nv_bfloat16 h1 = __float2bfloat16(v.y);
            __nv_bfloat16 h2 = __float2bfloat16(v.z);
            __nv_bfloat16 h3 = __float2bfloat16(v.w);
            __nv_bfloat16 l0 = __float2bfloat16(v.x - __bfloat162float(h0));
            __nv_bfloat16 l1 = __float2bfloat16(v.y - __bfloat162float(h1));
            __nv_bfloat16 l2 = __float2bfloat16(v.z - __bfloat162float(h2));
            __nv_bfloat16 l3 = __float2bfloat16(v.w - __bfloat162float(h3));
            uint2 hp, lp;
            hp.x = (uint32_t)__bfloat16_as_ushort(h0) | ((uint32_t)__bfloat16_as_ushort(h1) << 16);
            hp.y = (uint32_t)__bfloat16_as_ushort(h2) | ((uint32_t)__bfloat16_as_ushort(h3) << 16);
            lp.x = (uint32_t)__bfloat16_as_ushort(l0) | ((uint32_t)__bfloat16_as_ushort(l1) << 16);
            lp.y = (uint32_t)__bfloat16_as_ushort(l2) | ((uint32_t)__bfloat16_as_ushort(l3) << 16);
            uint32_t off = (uint32_t)r*144 + (uint32_t)q*8;
            *(uint2*)(sm + GA(buf) + off)        = hp;
            *(uint2*)(sm + GA(buf) + 9216 + off) = lp;
        }
        CPA_WAIT0();
        __syncthreads();

        if (kc < 3) {
            const float4* Ag = (const float4*)(A + m0*256 + (kc + 1)*64);
#pragma unroll
            for (int i = 0; i < 4; i++) {
                int f = tid + 256*i;
                av[i] = Ag[(f >> 4)*64 + (f & 15)];
            }
            int nb = buf ^ 1;
#pragma unroll
            for (int i = 0; i < 8; i++) {
                int f = tid + 256*i;
                int r = f >> 3, q = f & 7;
                uint32_t off = (uint32_t)r*144 + (uint32_t)q*16;
                cpa16(sb + GBH(nb) + off, WtH + (r << 8) + (kc + 1)*64 + q*8);
                cpa16(sb + GBL(nb) + off, WtL + (r << 8) + (kc + 1)*64 + q*8);
            }
            CPA_COMMIT();
        }

        uint32_t aB = sb + GA(buf) + aOff;
        uint32_t bB = sb + GBH(buf) + bOff;
#pragma unroll
        for (int ks = 0; ks < 4; ks++) {
            uint32_t aH[2][4], aL[2][4], bH[4][4], bL[4][4];
#pragma unroll
            for (int i = 0; i < 2; i++) {
                ldsm4(aH[i][0], aH[i][1], aH[i][2], aH[i][3],
                      aB + (uint32_t)i*2304 + (uint32_t)ks*32);
                ldsm4(aL[i][0], aL[i][1], aL[i][2], aL[i][3],
                      aB + 9216u + (uint32_t)i*2304 + (uint32_t)ks*32);
            }
#pragma unroll
            for (int j = 0; j < 4; j++) {
                ldsm4(bH[j][0], bH[j][1], bH[j][2], bH[j][3],
                      bB + (uint32_t)j*2304 + (uint32_t)ks*32);
                ldsm4(bL[j][0], bL[j][1], bL[j][2], bL[j][3],
                      bB + 36864u + (uint32_t)j*2304 + (uint32_t)ks*32);
            }
#pragma unroll
            for (int i = 0; i < 2; i++)
#pragma unroll
                for (int j = 0; j < 4; j++) {
                    mma16816(acc[i][2*j],   aH[i], &bH[j][0]);
                    mma16816(acc[i][2*j+1], aH[i], &bH[j][2]);
                    mma16816(acc[i][2*j],   aH[i], &bL[j][0]);
                    mma16816(acc[i][2*j+1], aH[i], &bL[j][2]);
                    mma16816(acc[i][2*j],   aL[i], &bH[j][0]);
                    mma16816(acc[i][2*j+1], aL[i], &bH[j][2]);
                }
        }
        __syncthreads();
    }

    // epilogue
    int tr = lane >> 2, tc = (lane & 3) * 2;
    float2 bb[8];
#pragma unroll
    for (int j = 0; j < 8; j++) {
        int cl = wn + 8*j + tc;
        bb[j].x = __ldg(&bias[cl]);
        bb[j].y = __ldg(&bias[cl+1]);
    }
    if (mode == 0) {
#pragma unroll
        for (int i = 0; i < 2; i++) {
            int r0 = m0 + wm + 16*i + tr;
#pragma unroll
            for (int j = 0; j < 8; j++) {
                int cl = wn + 8*j + tc;
                float2 o0, o1;
                o0.x = acc[i][j][0] + bb[j].x; o0.y = acc[i][j][1] + bb[j].y;
                o1.x = acc[i][j][2] + bb[j].x; o1.y = acc[i][j][3] + bb[j].y;
                *(float2*)&C[r0*256 + cl]     = o0;
                *(float2*)&C[(r0+8)*256 + cl] = o1;
            }
        }
    } else {
        float scale = (y == 0) ? RSQRT_DK : 1.f;
        __nv_bfloat16 *iH, *iL;
        if (y == 0)      { iH = g_iQH; iL = g_iQL; }
        else if (y == 1) { iH = g_iKH; iL = g_iKL; }
        else             { iH = g_iVH; iL = g_iVL; }
#pragma unroll
        for (int i = 0; i < 2; i++) {
            int r0 = m0 + wm + 16*i + tr;
            int r1 = r0 + 8;
            int ga0 = r0 / 336, s0 = r0 - ga0*336;
            int ga1 = r1 / 336, s1 = r1 - ga1*336;
#pragma unroll
            for (int j = 0; j < 8; j++) {
                int cl = wn + 8*j + tc;
                int hh = cl >> 5, dd = cl & 31;
                float v0 = (acc[i][j][0] + bb[j].x) * scale;
                float v1 = (acc[i][j][1] + bb[j].y) * scale;
                float v2 = (acc[i][j][2] + bb[j].x) * scale;
                float v3 = (acc[i][j][3] + bb[j].y) * scale;
                __nv_bfloat162 h01 = __floats2bfloat162_rn(v0, v1);
                __nv_bfloat162 h23 = __floats2bfloat162_rn(v2, v3);
                int idx0 = (((ga0 << 3) + hh)*336 + s0)*32 + dd;
                int idx1 = (((ga1 << 3) + hh)*336 + s1)*32 + dd;
                *(uint32_t*)&iH[idx0] = *(uint32_t*)&h01;
                *(uint32_t*)&iL[idx0] = pk_bf2(v0 - __bfloat162float(h01.x),
                                               v1 - __bfloat162float(h01.y));
                *(uint32_t*)&iH[idx1] = *(uint32_t*)&h23;
                *(uint32_t*)&iL[idx1] = pk_bf2(v2 - __bfloat162float(h23.x),
                                               v3 - __bfloat162float(h23.y));
            }
        }
    }
}

__global__ void __launch_bounds__(256, 1)
k_tgemm_qkv(const float* __restrict__ bq, const float* __restrict__ bk,
            const float* __restrict__ bv, int mode) {
    extern __shared__ char sm[];
    int y = blockIdx.y;
    const __nv_bfloat16* WH = &g_WtH[y*65536];
    const __nv_bfloat16* WL = &g_WtL[y*65536];
    const float* bias = (y == 0) ? bq : (y == 1) ? bk : bv;
    float* C = (y == 0) ? g_Q : (y == 1) ? g_K : g_V;
    tgemm_body(sm, g_E, WH, WL, bias, C, mode, y);
}

// ---------------- Wo GEMM (32x256) with fused residual + LN (+second LN) ----------------
#define WA(buf)   ((buf)*9216)            // A hi@0, lo@+4608
#define WBH(buf)  (18432 + (buf)*73728)
#define WBL(buf)  (18432 + (buf)*73728 + 36864)
#define WRED      165888
#define SMEM_WO   166912

__global__ void __launch_bounds__(256, 1)
k_wo(const float* __restrict__ bo,
     const float* __restrict__ g1v, const float* __restrict__ b1v,
     const float* __restrict__ g2v, const float* __restrict__ b2v, int dbl) {
    extern __shared__ char sm[];
    const int tid = threadIdx.x;
    const int wid = tid >> 5, lane = tid & 31;
    const int m0 = blockIdx.x * 32;
    const int wm = (wid & 1) * 16;
    const int wn = (wid >> 1) * 64;
    const int ng = wid >> 1;
    uint32_t sb = smem_u32(sm);
    const __nv_bfloat16* WtH = &g_WtH[3*65536];
    const __nv_bfloat16* WtL = &g_WtL[3*65536];

    float acc[8][4];
#pragma unroll
    for (int j = 0; j < 8; j++)
#pragma unroll
        for (int q = 0; q < 4; q++) acc[j][q] = 0.f;

    uint32_t aRow = wm + (lane & 7) + ((lane >> 3) & 1) * 8;
    uint32_t aOff = aRow*144 + ((lane >> 4) & 1)*16;
    uint32_t bRow = wn + (lane & 7) + ((lane >> 4) & 1) * 8;
    uint32_t bOff = bRow*144 + ((lane >> 3) & 1)*16;

    // prologue
    float4 av[2];
    {
        const float4* Ag = (const float4*)(g_O + m0*256);
#pragma unroll
        for (int i = 0; i < 2; i++) {
            int f = tid + 256*i;
            av[i] = Ag[(f >> 4)*64 + (f & 15)];
        }
#pragma unroll
        for (int i = 0; i < 8; i++) {
            int f = tid + 256*i;
            int r = f >> 3, q = f & 7;
            uint32_t off = (uint32_t)r*144 + (uint32_t)q*16;
            cpa16(sb + WBH(0) + off, WtH + (r << 8) + q*8);
            cpa16(sb + WBL(0) + off, WtL + (r << 8) + q*8);
        }
        CPA_COMMIT();
    }

#pragma unroll
    for (int kc = 0; kc < 4; kc++) {
        int buf = kc & 1;
#pragma unroll
        for (int i = 0; i < 2; i++) {
            int f = tid + 256*i;
            int r = f >> 4, q = f & 15;
            float4 v = av[i];
            __nv_bfloat16 h0 = __float2bfloat16(v.x);
            __nv_bfloat16 h1 = __float2bfloat16(v.y);
            __nv_bfloat16 h2 = __float2bfloat16(v.z);
            __nv_bfloat16 h3 = __float2bfloat16(v.w);
            __nv_bfloat16 l0 = __float2bfloat16(v.x - __bfloat162float(h0));
            __nv_bfloat16 l1 = __float2bfloat16(v.y - __bfloat162float(h1));
            __nv_bfloat16 l2 = __float2bfloat16(v.z - __bfloat162float(h2));
            __nv_bfloat16 l3 = __float2bfloat16(v.w - __bfloat162float(h3));
            uint2 hp, lp;
            hp.x = (uint32_t)__bfloat16_as_ushort(h0) | ((uint32_t)__bfloat16_as_ushort(h1) << 16);
            hp.y = (uint32_t)__bfloat16_as_ushort(h2) | ((uint32_t)__bfloat16_as_ushort(h3) << 16);
            lp.x = (uint32_t)__bfloat16_as_ushort(l0) | ((uint32_t)__bfloat16_as_ushort(l1) << 16);
            lp.y = (uint32_t)__bfloat16_as_ushort(l2) | ((uint32_t)__bfloat16_as_ushort(l3) << 16);
            uint32_t off = (uint32_t)r*144 + (uint32_t)q*8;
            *(uint2*)(sm + WA(buf) + off)        = hp;
            *(uint2*)(sm + WA(buf) + 4608 + off) = lp;
        }
        CPA_WAIT0();
        __syncthreads();

        if (kc < 3) {
            const float4* Ag = (const float4*)(g_O + m0*256 + (kc + 1)*64);
#pragma unroll
            for (int i = 0; i < 2; i++) {
                int f = tid + 256*i;
                av[i] = Ag[(f >> 4)*64 + (f & 15)];
            }
            int nb = buf ^ 1;
#pragma unroll
            for (int i = 0; i < 8; i++) {
                int f = tid + 256*i;
                int r = f >> 3, q = f & 7;
                uint32_t off = (uint32_t)r*144 + (uint32_t)q*16;
                cpa16(sb + WBH(nb) + off, WtH + (r << 8) + (kc + 1)*64 + q*8);
                cpa16(sb + WBL(nb) + off, WtL + (r << 8) + (kc + 1)*64 + q*8);
            }
            CPA_COMMIT();
        }

        uint32_t aB = sb + WA(buf) + aOff;
        uint32_t bB = sb + WBH(buf) + bOff;
#pragma unroll
        for (int ks = 0; ks < 4; ks++) {
            uint32_t aH[4], aL[4], bH[4][4], bL[4][4];
            ldsm4(aH[0], aH[1], aH[2], aH[3], aB + (uint32_t)ks*32);
            ldsm4(aL[0], aL[1], aL[2], aL[3], aB + 4608u + (uint32_t)ks*32);
#pragma unroll
            for (int j = 0; j < 4; j++) {
                ldsm4(bH[j][0], bH[j][1], bH[j][2], bH[j][3],
                      bB + (uint32_t)j*2304 + (uint32_t)ks*32);
                ldsm4(bL[j][0], bL[j][1], bL[j][2], bL[j][3],
                      bB + 36864u + (uint32_t)j*2304 + (uint32_t)ks*32);
            }
#pragma unroll
            for (int j = 0; j < 4; j++) {
                mma16816(acc[2*j],   aH, &bH[j][0]);
                mma16816(acc[2*j+1], aH, &bH[j][2]);
                mma16816(acc[2*j],   aH, &bL[j][0]);
                mma16816(acc[2*j+1], aH, &bL[j][2]);
                mma16816(acc[2*j],   aL, &bH[j][0]);
                mma16816(acc[2*j+1], aL, &bH[j][2]);
            }
        }
        __syncthreads();
    }

    // epilogue: x = acc + bias + residual; then LN (and optional second LN)
    int tr = lane >> 2, tc2 = (lane & 3) * 2;
    int rlo = m0 + wm + tr, rhi = rlo + 8;
    int rl = wm + tr;
    float* sRed = (float*)(sm + WRED);

#pragma unroll
    for (int j = 0; j < 8; j++) {
        int cl = wn + 8*j + tc2;
        float2 e0 = *(const float2*)&g_E[rlo*256 + cl];
        float2 e1 = *(const float2*)&g_E[rhi*256 + cl];
        float b0 = __ldg(&bo[cl]), b1 = __ldg(&bo[cl+1]);
        acc[j][0] += b0 + e0.x; acc[j][1] += b1 + e0.y;
        acc[j][2] += b0 + e1.x; acc[j][3] += b1 + e1.y;
    }

    int rounds = 1 + dbl;
    for (int rd = 0; rd < rounds; rd++) {
        const float* gv  = rd ? g2v : g1v;
        const float* bv2 = rd ? b2v : b1v;
        float s0 = 0.f, q0 = 0.f, s1 = 0.f, q1 = 0.f;
#pragma unroll
        for (int j = 0; j < 8; j++) {
            s0 += acc[j][0] + acc[j][1];
            q0 += acc[j][0]*acc[j][0] + acc[j][1]*acc[j][1];
            s1 += acc[j][2] + acc[j][3];
            q1 += acc[j][2]*acc[j][2] + acc[j][3]*acc[j][3];
        }
#pragma unroll
        for (int o = 1; o <= 2; o <<= 1) {
            s0 += __shfl_xor_sync(0xffffffffu, s0, o);
            q0 += __shfl_xor_sync(0xffffffffu, q0, o);
            s1 += __shfl_xor_sync(0xffffffffu, s1, o);
            q1 += __shfl_xor_sync(0xffffffffu, q1, o);
        }
        if ((lane & 3) == 0) {
            sRed[(rl*4 + ng)*2]         = s0;
            sRed[(rl*4 + ng)*2 + 1]     = q0;
            sRed[((rl+8)*4 + ng)*2]     = s1;
            sRed[((rl+8)*4 + ng)*2 + 1] = q1;
        }
        __syncthreads();
        float S0 = 0.f, Q0 = 0.f, S1 = 0.f, Q1 = 0.f;
#pragma unroll
        for (int n = 0; n < 4; n++) {
            S0 += sRed[(rl*4 + n)*2];     Q0 += sRed[(rl*4 + n)*2 + 1];
            S1 += sRed[((rl+8)*4 + n)*2]; Q1 += sRed[((rl+8)*4 + n)*2 + 1];
        }
        __syncthreads();
        float mu0 = S0 * (1.f/256.f);
        float r0  = rsqrtf(Q0*(1.f/256.f) - mu0*mu0 + 1e-5f);
        float mu1 = S1 * (1.f/256.f);
        float r1  = rsqrtf(Q1*(1.f/256.f) - mu1*mu1 + 1e-5f);
#pragma unroll
        for (int j = 0; j < 8; j++) {
            int cl = wn + 8*j + tc2;
            float gg0 = __ldg(&gv[cl]), gg1 = __ldg(&gv[cl+1]);
            float bb0 = __ldg(&bv2[cl]), bb1 = __ldg(&bv2[cl+1]);
            acc[j][0] = (acc[j][0] - mu0)*r0*gg0 + bb0;
            acc[j][1] = (acc[j][1] - mu0)*r0*gg1 + bb1;
            acc[j][2] = (acc[j][2] - mu1)*r1*gg0 + bb0;
            acc[j][3] = (acc[j][3] - mu1)*r1*gg1 + bb1;
        }
    }
#pragma unroll
    for (int j = 0; j < 8; j++) {
        int cl = wn + 8*j + tc2;
        float2 o0, o1;
        o0.x = acc[j][0]; o0.y = acc[j][1];
        o1.x = acc[j][2]; o1.y = acc[j][3];
        *(float2*)&g_E[rlo*256 + cl] = o0;
        *(float2*)&g_E[rhi*256 + cl] = o1;
    }
}

// ---------------- time attention: tensor-core flash from bf16 images ----------------
#define KT 48
__global__ void __launch_bounds__(256) k_attn_time() {
    __shared__ __nv_bfloat16 sQH[128*40], sQL[128*40];
    __shared__ __nv_bfloat16 sKH[48*40],  sKL[48*40];
    __shared__ __nv_bfloat16 sVH[32*56],  sVL[32*56];

    int g  = blockIdx.z;
    int h  = blockIdx.y;
    int qb = blockIdx.x * 128;
    int tid = threadIdx.x;
    int wid = tid >> 5, lane = tid & 31;
    const int base = ((g*8 + h)*336)*32;

    uint32_t uQH = smem_u32(sQH), uQL = smem_u32(sQL);
    uint32_t uKH = smem_u32(sKH), uKL = smem_u32(sKL);
    uint32_t uVH = smem_u32(sVH), uVL = smem_u32(sVL);

    // stage Q (pure copies — already bf16 hi/lo, pre-scaled)
#pragma unroll
    for (int i = 0; i < 2; i++) {
        int idx = tid + 256*i;          // 512
        int r = idx >> 2, q = idx & 3;
        int qi = qb + r; if (qi > 335) qi = 335;
        *(uint4*)&sQH[r*40 + q*8] = *(const uint4*)&g_iQH[base + qi*32 + q*8];
        *(uint4*)&sQL[r*40 + q*8] = *(const uint4*)&g_iQL[base + qi*32 + q*8];
    }
    __syncthreads();

    uint32_t aQoff = (uint32_t)(wid*16 + (lane & 7) + ((lane >> 3) & 1)*8)*80
                   + ((lane >> 4) & 1)*16;
    uint32_t qH[2][4], qL[2][4];
#pragma unroll
    for (int ks = 0; ks < 2; ks++) {
        ldsm4(qH[ks][0], qH[ks][1], qH[ks][2], qH[ks][3], uQH + aQoff + ks*32);
        ldsm4(qL[ks][0], qL[ks][1], qL[ks][2], qL[ks][3], uQL + aQoff + ks*32);
    }

    float o[4][4];
#pragma unroll
    for (int j = 0; j < 4; j++)
#pragma unroll
        for (int q = 0; q < 4; q++) o[j][q] = 0.f;
    float m0 = -1e30f, m1 = -1e30f, sum0 = 0.f, sum1 = 0.f;

    uint32_t kOff = (uint32_t)((lane & 7) + ((lane >> 4) & 1)*8)*80 + ((lane >> 3) & 1)*16;
    uint32_t vOff = (uint32_t)((lane & 7) + ((lane >> 4) & 1)*8)*112 + ((lane >> 3) & 1)*16;

    // stage K/V tile 0 (copies + V transpose)  [p mod 768 done explicitly: 768 != pow2]
#pragma unroll
    for (int i = 0; i < 6; i++) {
        int p = tid + 256*i;            // 0..1535
        int img = p >= 768;
        int q = img ? (p - 768) : p;
        int r = q >> 4, c2 = (q & 15)*2;
        const __nv_bfloat16* ks = img ? g_iKL : g_iKH;
        *(uint32_t*)&((img ? sKL : sKH)[r*40 + c2]) =
            *(const uint32_t*)&ks[base + r*32 + c2];
        const __nv_bfloat16* vs = img ? g_iVL : g_iVH;
        uint32_t vv = *(const uint32_t*)&vs[base + r*32 + c2];
        __nv_bfloat162 pv = *(__nv_bfloat162*)&vv;
        __nv_bfloat16* vd = img ? sVL : sVH;
        vd[c2*56 + r]     = pv.x;
        vd[(c2+1)*56 + r] = pv.y;
    }
    __syncthreads();

    uint32_t pK[6], pV[6];
    for (int kt = 0; kt < 7; kt++) {
        if (kt < 6) {
            int kb = (kt + 1)*KT;
#pragma unroll
            for (int i = 0; i < 6; i++) {
                int p = tid + 256*i;
                int img = p >= 768;
                int q = img ? (p - 768) : p;
                int r = q >> 4, c2 = (q & 15)*2;
                pK[i] = *(const uint32_t*)&((img ? g_iKL : g_iKH)[base + (kb + r)*32 + c2]);
                pV[i] = *(const uint32_t*)&((img ? g_iVL : g_iVH)[base + (kb + r)*32 + c2]);
            }
        }

        // scores S (16 x 48) = Q K^T, 3-term bf16 split
        float sc[6][4];
#pragma unroll
        for (int j = 0; j < 6; j++)
#pragma unroll
            for (int q = 0; q < 4; q++) sc[j][q] = 0.f;
#pragma unroll
        for (int ks = 0; ks < 2; ks++) {
#pragma unroll
            for (int ng = 0; ng < 3; ng++) {
                uint32_t bH[4], bL[4];
                ldsm4(bH[0], bH[1], bH[2], bH[3], uKH + kOff + ng*(16*80) + ks*32);
                ldsm4(bL[0], bL[1], bL[2], bL[3], uKL + kOff + ng*(16*80) + ks*32);
                mma16816(sc[2*ng],   qH[ks], &bH[0]);
                mma16816(sc[2*ng+1], qH[ks], &bH[2]);
                mma16816(sc[2*ng],   qH[ks], &bL[0]);
                mma16816(sc[2*ng+1], qH[ks], &bL[2]);
                mma16816(sc[2*ng],   qL[ks], &bH[0]);
                mma16816(sc[2*ng+1], qL[ks], &bH[2]);
            }
        }

        // online softmax
        float t0 = -1e30f, t1 = -1e30f;
#pragma unroll
        for (int j = 0; j < 6; j++) {
            t0 = fmaxf(t0, fmaxf(sc[j][0], sc[j][1]));
            t1 = fmaxf(t1, fmaxf(sc[j][2], sc[j][3]));
        }
        t0 = fmaxf(t0, __shfl_xor_sync(0xffffffffu, t0, 1));
        t0 = fmaxf(t0, __shfl_xor_sync(0xffffffffu, t0, 2));
        t1 = fmaxf(t1, __shfl_xor_sync(0xffffffffu, t1, 1));
        t1 = fmaxf(t1, __shfl_xor_sync(0xffffffffu, t1, 2));
        float nm0 = fmaxf(m0, t0), nm1 = fmaxf(m1, t1);
        float c0 = __expf(m0 - nm0), c1 = __expf(m1 - nm1);
        float ts0 = 0.f, ts1 = 0.f;
#pragma unroll
        for (int j = 0; j < 6; j++) {
            sc[j][0] = __expf(sc[j][0] - nm0);
            sc[j][1] = __expf(sc[j][1] - nm0);
            sc[j][2] = __expf(sc[j][2] - nm1);
            sc[j][3] = __expf(sc[j][3] - nm1);
            ts0 += sc[j][0] + sc[j][1];
            ts1 += sc[j][2] + sc[j][3];
        }
        sum0 = sum0*c0 + ts0;
        sum1 = sum1*c1 + ts1;
#pragma unroll
        for (int j = 0; j < 4; j++) {
            o[j][0] *= c0; o[j][1] *= c0; o[j][2] *= c1; o[j][3] *= c1;
        }
        m0 = nm0; m1 = nm1;

        // PV, 3-term split
#pragma unroll
        for (int kb = 0; kb < 3; kb++) {
            uint32_t aP[4], aR[4];
#pragma unroll
            for (int t = 0; t < 2; t++) {
                int j = 2*kb + t;
                float x0 = sc[j][0], x1 = sc[j][1], x2 = sc[j][2], x3 = sc[j][3];
                __nv_bfloat162 h01 = __floats2bfloat162_rn(x0, x1);
                __nv_bfloat162 h23 = __floats2bfloat162_rn(x2, x3);
                aP[2*t]   = *(uint32_t*)&h01;
                aP[2*t+1] = *(uint32_t*)&h23;
                aR[2*t]   = pk_bf2(x0 - __bfloat162float(h01.x),
                                   x1 - __bfloat162float(h01.y));
                aR[2*t+1] = pk_bf2(x2 - __bfloat162float(h23.x),
                                   x3 - __bfloat162float(h23.y));
            }
#pragma unroll
            for (int ng = 0; ng < 2; ng++) {
                uint32_t vH[4], vL[4];
                ldsm4(vH[0], vH[1], vH[2], vH[3], uVH + vOff + ng*(16*112) + kb*32);
                ldsm4(vL[0], vL[1], vL[2], vL[3], uVL + vOff + ng*(16*112) + kb*32);
                mma16816(o[2*ng],   aP, &vH[0]);
                mma16816(o[2*ng+1], aP, &vH[2]);
                mma16816(o[2*ng],   aP, &vL[0]);
                mma16816(o[2*ng+1], aP, &vL[2]);
                mma16816(o[2*ng],   aR, &vH[0]);
                mma16816(o[2*ng+1], aR, &vH[2]);
            }
        }
        __syncthreads();
        if (kt < 6) {
#pragma unroll
            for (int i = 0; i < 6; i++) {
                int p = tid + 256*i;
                int img = p >= 768;
                int q = img ? (p - 768) : p;
                int r = q >> 4, c2 = (q & 15)*2;
                *(uint32_t*)&((img ? sKL : sKH)[r*40 + c2]) = pK[i];
                __nv_bfloat162 pv = *(__nv_bfloat162*)&pV[i];
                __nv_bfloat16* vd = img ? sVL : sVH;
                vd[c2*56 + r]     = pv.x;
                vd[(c2+1)*56 + r] = pv.y;
            }
            __syncthreads();
        }
    }

    // finalize
    sum0 += __shfl_xor_sync(0xffffffffu, sum0, 1);
    sum0 += __shfl_xor_sync(0xffffffffu, sum0, 2);
    sum1 += __shfl_xor_sync(0xffffffffu, sum1, 1);
    sum1 += __shfl_xor_sync(0xffffffffu, sum1, 2);
    float inv0 = 1.f / sum0, inv1 = 1.f / sum1;
    int q0 = qb + wid*16 + (lane >> 2);
    int q1 = q0 + 8;
    int cbase = h*32 + 2*(lane & 3);
#pragma unroll
    for (int j = 0; j < 4; j++) {
        int col = cbase + 8*j;
        if (q0 < 336) {
            float2 w0; w0.x = o[j][0]*inv0; w0.y = o[j][1]*inv0;
            *(float2*)&g_O[(g*SS + q0)*DD + col] = w0;
        }
        if (q1 < 336) {
            float2 w1; w1.x = o[j][2]*inv1; w1.y = o[j][3]*inv1;
            *(float2*)&g_O[(g*SS + q1)*DD + col] = w1;
        }
    }
}

// ---------------- variable attention (L=8, fp32 path) ----------------
__global__ void __launch_bounds__(64) k_attn_var() {
    __shared__ __align__(16) float Ks[8][256];
    __shared__ __align__(16) float Vs[8][256];

    int bs = blockIdx.x;
    int b = bs / SS;
    int s = bs - b*SS;
    int tid = threadIdx.x;

#pragma unroll
    for (int i = 0; i < 8; i++) {
        int f = tid + 64*i;
        int v = f >> 6;
        int dq = f & 63;
        int ga = ((b*VV + v)*SS + s)*DD + dq*4;
        *(float4*)&Ks[v][dq*4] = *(const float4*)&g_K[ga];
        *(float4*)&Vs[v][dq*4] = *(const float4*)&g_V[ga];
    }
    __syncthreads();

    int qv = tid & 7;
    int h  = tid >> 3;
    const float* qp = &g_Q[((b*VV + qv)*SS + s)*DD + h*32];
    float q[32];
#pragma unroll
    for (int i = 0; i < 8; i++) {
        float4 v4 = *(const float4*)&qp[i*4];
        q[i*4+0] = v4.x; q[i*4+1] = v4.y; q[i*4+2] = v4.z; q[i*4+3] = v4.w;
    }
    float sc[8];
    float mx = -1e30f;
#pragma unroll
    for (int v = 0; v < 8; v++) {
        float t = 0.f;
#pragma unroll
        for (int d = 0; d < 32; d++) t += q[d]*Ks[v][h*32 + d];
        t *= RSQRT_DK;
        sc[v] = t;
        mx = fmaxf(mx, t);
    }
    float sum = 0.f;
#pragma unroll
    for (int v = 0; v < 8; v++) { sc[v] = __expf(sc[v] - mx); sum += sc[v]; }
    float inv = 1.f / sum;

    float o[32];
#pragma unroll
    for (int d = 0; d < 32; d++) o[d] = 0.f;
#pragma unroll
    for (int v = 0; v < 8; v++)
#pragma unroll
        for (int d = 0; d < 32; d++) o[d] += sc[v]*Vs[v][h*32 + d];

    float* op = &g_O[((b*VV + qv)*SS + s)*DD + h*32];
#pragma unroll
    for (int i = 0; i < 8; i++) {
        float4 v4;
        v4.x = o[i*4+0]*inv; v4.y = o[i*4+1]*inv;
        v4.z = o[i*4+2]*inv; v4.w = o[i*4+3]*inv;
        *(float4*)&op[i*4] = v4;
    }
}

// ---------------- final projection ----------------
__global__ void k_out_init(const float* __restrict__ pb, float* __restrict__ out) {
    int i = blockIdx.x*256 + threadIdx.x;
    if (i < BB*PP*VV) {
        int p = (i % (PP*VV)) >> 3;
        out[i] = pb[p];
    }
}

__global__ void __launch_bounds__(256) k_proj(const float* __restrict__ W,
                                              float* __restrict__ out) {
    __shared__ float Ws[64][96];
    __shared__ float Es[16][64];
    int k0 = blockIdx.x * 512;
    int tid = threadIdx.x;

    float acc[6];
    const float* erow[6];
    int wcol[6], oidx[6];
#pragma unroll
    for (int i = 0; i < 6; i++) {
        int qq = tid + 256*i;
        int bv = qq / 96;
        int p  = qq - bv*96;
        acc[i] = 0.f;
        erow[i] = &Es[bv][0];
        wcol[i] = p;
        oidx[i] = (bv >> 3)*(PP*VV) + p*VV + (bv & 7);
    }

    for (int kt = 0; kt < 8; kt++) {
        int kb = k0 + kt*64;
        __syncthreads();
#pragma unroll
        for (int i = 0; i < 6; i++) {
            int f = tid + 256*i;
            int kk = f / 24;
            int pq = f - kk*24;
            *(float4*)&Ws[kk][pq*4] = *(const float4*)&W[(kb + kk)*PP + pq*4];
        }
        {
            int bv = tid >> 4;
            int kq = tid & 15;
            *(float4*)&Es[bv][kq*4] = *(const float4*)&g_E[bv*SD + kb + kq*4];
        }
        __syncthreads();
        for (int kk = 0; kk < 64; kk++) {
#pragma unroll
            for (int i = 0; i < 6; i++)
                acc[i] += erow[i][kk] * Ws[kk][wcol[i]];
        }
    }
#pragma unroll
    for (int i = 0; i < 6; i++)
        atomicAdd(&out[oidx[i]], acc[i]);
}

// ---------------- launch ----------------
extern "C" void kernel_launch(void* const* d_in, const int* in_sizes, int n_in,
                              void* d_out, int out_size) {
    const float* x      = (const float*)d_in[0];
    const float* emb_w  = (const float*)d_in[1];
    const float* emb_b  = (const float*)d_in[2];
    const float* Wq     = (const float*)d_in[3];
    const float* bq     = (const float*)d_in[4];
    const float* Wk     = (const float*)d_in[5];
    const float* bk     = (const float*)d_in[6];
    const float* Wv     = (const float*)d_in[7];
    const float* bv     = (const float*)d_in[8];
    const float* Wo     = (const float*)d_in[9];
    const float* bo     = (const float*)d_in[10];
    const float* ln1_g  = (const float*)d_in[11];
    const float* ln1_b  = (const float*)d_in[12];
    const float* norm_g = (const float*)d_in[13];
    const float* norm_b = (const float*)d_in[14];
    const float* proj_w = (const float*)d_in[15];
    const float* proj_b = (const float*)d_in[16];
    float* out = (float*)d_out;

    cudaFuncSetAttribute(k_tgemm_qkv, cudaFuncAttributeMaxDynamicSharedMemorySize, SMEM_GEMM);
    cudaFuncSetAttribute(k_wo,        cudaFuncAttributeMaxDynamicSharedMemorySize, SMEM_WO);

    k_prep<<<dim3(256, 4), 256>>>(Wq, Wk, Wv, Wo);
    k_embed<<<NT, 256>>>(x, emb_w, emb_b);

    for (int it = 0; it < 10; it++) {
        // phase A: attention over time axis (bf16 image path)
        k_tgemm_qkv<<<dim3(84, 3), 256, SMEM_GEMM>>>(bq, bk, bv, 1);
        k_attn_time<<<dim3(3, 8, 16), 256>>>();
        k_wo<<<168, 256, SMEM_WO>>>(bo, ln1_g, ln1_b, norm_g, norm_b, 1);
        // phase B: attention over variable axis (fp32 path)
        k_tgemm_qkv<<<dim3(84, 3), 256, SMEM_GEMM>>>(bq, bk, bv, 0);
        k_attn_var<<<BB*SS, 64>>>();
        k_wo<<<168, 256, SMEM_WO>>>(bo, ln1_g, ln1_b, norm_g, norm_b, 0);
    }

    k_out_init<<<6, 256>>>(proj_b, out);
    k_proj<<<SD/512, 256>>>(proj_w, out);
}

// round 12
// speedup vs baseline: 1.0699x; 1.0699x over previous
#include <cuda_runtime.h>
#include <cuda_bf16.h>
#include <math.h>
#include <stdint.h>

// ---------------- problem constants ----------------
#define BB   2
#define SS   336
#define VV   8
#define DD   256
#define HH   8
#define DK   32
#define PP   96
#define NT   (BB*VV*SS)      // 5376 tokens
#define SD   (SS*DD)         // 86016
#define RSQRT_DK 0.17677669529663687f   // 1/sqrt(32)

// ---------------- scratch ----------------
__device__ float g_E[NT*DD];
__device__ float g_Q[NT*DD];
__device__ float g_K[NT*DD];
__device__ float g_V[NT*DD];
__device__ float g_O[NT*DD];
// transposed bf16 weight images W^T[n][k], hi/lo split: [w(4)][256][256]
__device__ __align__(16) __nv_bfloat16 g_WtH[4*65536];
__device__ __align__(16) __nv_bfloat16 g_WtL[4*65536];
// phase-A QKV bf16 images: [(g*8+h)*336 + s]*32 + d  (Q pre-scaled by 1/sqrt(dk))
#define IMG_ELEMS (128*336*32)
__device__ __align__(16) __nv_bfloat16 g_iQH[IMG_ELEMS], g_iQL[IMG_ELEMS];
__device__ __align__(16) __nv_bfloat16 g_iKH[IMG_ELEMS], g_iKL[IMG_ELEMS];
__device__ __align__(16) __nv_bfloat16 g_iVH[IMG_ELEMS], g_iVL[IMG_ELEMS];

// ---------------- helpers ----------------
__device__ __forceinline__ uint32_t smem_u32(const void* p) {
    uint32_t a;
    asm("{ .reg .u64 t; cvta.to.shared.u64 t, %1; cvt.u32.u64 %0, t; }" : "=r"(a) : "l"(p));
    return a;
}
__device__ __forceinline__ void ldsm4(uint32_t& r0, uint32_t& r1, uint32_t& r2, uint32_t& r3,
                                      uint32_t a) {
    asm volatile("ldmatrix.sync.aligned.m8n8.x4.shared.b16 {%0,%1,%2,%3}, [%4];"
        : "=r"(r0), "=r"(r1), "=r"(r2), "=r"(r3) : "r"(a));
}
__device__ __forceinline__ void mma16816(float* c, const uint32_t* a, const uint32_t* b) {
    asm volatile("mma.sync.aligned.m16n8k16.row.col.f32.bf16.bf16.f32 "
        "{%0,%1,%2,%3}, {%4,%5,%6,%7}, {%8,%9}, {%0,%1,%2,%3};"
        : "+f"(c[0]), "+f"(c[1]), "+f"(c[2]), "+f"(c[3])
        : "r"(a[0]), "r"(a[1]), "r"(a[2]), "r"(a[3]), "r"(b[0]), "r"(b[1]));
}
__device__ __forceinline__ void cpa16(uint32_t dst, const void* src) {
    asm volatile("cp.async.cg.shared.global [%0], [%1], 16;" :: "r"(dst), "l"(src));
}
#define CPA_COMMIT() asm volatile("cp.async.commit_group;" ::: "memory")
#define CPA_WAIT0()  asm volatile("cp.async.wait_group 0;" ::: "memory")

__device__ __forceinline__ uint32_t pk_bf2(float lo, float hi) {
    __nv_bfloat162 h = __floats2bfloat162_rn(lo, hi);
    return *(uint32_t*)&h;
}

// ---------------- embed ----------------
__global__ void k_embed(const float* __restrict__ x,
                        const float* __restrict__ ew,
                        const float* __restrict__ eb) {
    int idx = blockIdx.x * 256 + threadIdx.x;
    int d = idx & 255;
    int t = idx >> 8;
    int b = t / (VV*SS);
    int r = t - b*(VV*SS);
    int v = r / SS;
    int s = r - v*SS;
    g_E[idx] = x[(b*SS + s)*VV + v] * ew[d] + eb[d];
}

// ---------------- weight prep: W^T + bf16 hi/lo split ----------------
__global__ void k_prep(const float* __restrict__ Wq, const float* __restrict__ Wk,
                       const float* __restrict__ Wv, const float* __restrict__ Wo) {
    int e = blockIdx.x * 256 + threadIdx.x;   // 0..65535
    int w = blockIdx.y;
    int n = e >> 8, k = e & 255;
    const float* W = (w == 0) ? Wq : (w == 1) ? Wk : (w == 2) ? Wv : Wo;
    float a = W[k*256 + n];
    __nv_bfloat16 h = __float2bfloat16(a);
    __nv_bfloat16 l = __float2bfloat16(a - __bfloat162float(h));
    g_WtH[w*65536 + n*256 + k] = h;
    g_WtL[w*65536 + n*256 + k] = l;
}

// ---------------- pipelined mma.sync bf16x3 GEMM: 64x256 tile ----------------
// 8 warps (warp tile 32x64), K-chunks of 64, double-buffered + cp.async.
// mode 0: C = A@W + bias (fp32 out)
// mode 1: QKV phase-A image epilogue (bf16 hi/lo images, Q pre-scaled)
// mode 2: Wo epilogue: residual(g_E) + bias, LN (optionally second LN), out g_E
#define GA(buf)  ((buf)*18432)                        // A hi @+0, lo @+9216
#define GBH(buf) (36864 + (buf)*73728)
#define GBL(buf) (36864 + (buf)*73728 + 36864)
#define SMEM_GEMM 184320
#define SMEM_WO   (SMEM_GEMM + 2048)                  // + sRed (64 rows x 4 grp x 2)

__device__ __forceinline__ void tgemm_body(char* sm, const float* __restrict__ A,
                                           const __nv_bfloat16* __restrict__ WtH,
                                           const __nv_bfloat16* __restrict__ WtL,
                                           const float* __restrict__ bias,
                                           float* __restrict__ C,
                                           int mode, int y,
                                           const float* g1v, const float* b1v,
                                           const float* g2v, const float* b2v, int dbl) {
    const int tid = threadIdx.x;
    const int wid = tid >> 5, lane = tid & 31;
    const int m0 = blockIdx.x * 64;
    const int wm = (wid & 1) * 32;
    const int wn = (wid >> 1) * 64;
    uint32_t sb = smem_u32(sm);

    float acc[2][8][4];
#pragma unroll
    for (int i = 0; i < 2; i++)
#pragma unroll
        for (int j = 0; j < 8; j++)
#pragma unroll
            for (int q = 0; q < 4; q++) acc[i][j][q] = 0.f;

    uint32_t aRow = wm + (lane & 7) + ((lane >> 3) & 1) * 8;
    uint32_t aOff = aRow*144 + ((lane >> 4) & 1)*16;
    uint32_t bRow = wn + (lane & 7) + ((lane >> 4) & 1) * 8;
    uint32_t bOff = bRow*144 + ((lane >> 3) & 1)*16;

    // prologue: A chunk0 -> regs, B chunk0 -> cp.async buf0
    float4 av[4];
    {
        const float4* Ag = (const float4*)(A + m0*256);
#pragma unroll
        for (int i = 0; i < 4; i++) {
            int f = tid + 256*i;
            av[i] = Ag[(f >> 4)*64 + (f & 15)];
        }
#pragma unroll
        for (int i = 0; i < 8; i++) {
            int f = tid + 256*i;
            int r = f >> 3, q = f & 7;
            uint32_t off = (uint32_t)r*144 + (uint32_t)q*16;
            cpa16(sb + GBH(0) + off, WtH + (r << 8) + q*8);
            cpa16(sb + GBL(0) + off, WtL + (r << 8) + q*8);
        }
        CPA_COMMIT();
    }

#pragma unroll
    for (int kc = 0; kc < 4; kc++) {
        int buf = kc & 1;
#pragma unroll
        for (int i = 0; i < 4; i++) {
            int f = tid + 256*i;
            int r = f >> 4, q = f & 15;
            float4 v = av[i];
            __nv_bfloat16 h0 = __float2bfloat16(v.x);
            __nv_bfloat16 h1 = __float2bfloat16(v.y);
            __nv_bfloat16 h2 = __float2bfloat16(v.z);
            __nv_bfloat16 h3 = __float2bfloat16(v.w);
            __nv_bfloat16 l0 = __float2bfloat16(v.x - __bfloat162float(h0));
            __nv_bfloat16 l1 = __float2bfloat16(v.y - __bfloat162float(h1));
            __nv_bfloat16 l2 = __float2bfloat16(v.z - __bfloat162float(h2));
            __nv_bfloat16 l3 = __float2bfloat16(v.w - __bfloat162float(h3));
            uint2 hp, lp;
            hp.x = (uint32_t)__bfloat16_as_ushort(h0) | ((uint32_t)__bfloat16_as_ushort(h1) << 16);
            hp.y = (uint32_t)__bfloat16_as_ushort(h2) | ((uint32_t)__bfloat16_as_ushort(h3) << 16);
            lp.x = (uint32_t)__bfloat16_as_ushort(l0) | ((uint32_t)__bfloat16_as_ushort(l1) << 16);
            lp.y = (uint32_t)__bfloat16_as_ushort(l2) | ((uint32_t)__bfloat16_as_ushort(l3) << 16);
            uint32_t off = (uint32_t)r*144 + (uint32_t)q*8;
            *(uint2*)(sm + GA(buf) + off)        = hp;
            *(uint2*)(sm + GA(buf) + 9216 + off) = lp;
        }
        CPA_WAIT0();
        __syncthreads();

        if (kc < 3) {
            const float4* Ag = (const float4*)(A + m0*256 + (kc + 1)*64);
#pragma unroll
            for (int i = 0; i < 4; i++) {
                int f = tid + 256*i;
                av[i] = Ag[(f >> 4)*64 + (f & 15)];
            }
            int nb = buf ^ 1;
#pragma unroll
            for (int i = 0; i < 8; i++) {
                int f = tid + 256*i;
                int r = f >> 3, q = f & 7;
                uint32_t off = (uint32_t)r*144 + (uint32_t)q*16;
                cpa16(sb + GBH(nb) + off, WtH + (r << 8) + (kc + 1)*64 + q*8);
                cpa16(sb + GBL(nb) + off, WtL + (r << 8) + (kc + 1)*64 + q*8);
            }
            CPA_COMMIT();
        }

        uint32_t aB = sb + GA(buf) + aOff;
        uint32_t bB = sb + GBH(buf) + bOff;
#pragma unroll
        for (int ks = 0; ks < 4; ks++) {
            uint32_t aH[2][4], aL[2][4], bH[4][4], bL[4][4];
#pragma unroll
            for (int i = 0; i < 2; i++) {
                ldsm4(aH[i][0], aH[i][1], aH[i][2], aH[i][3],
                      aB + (uint32_t)i*2304 + (uint32_t)ks*32);
                ldsm4(aL[i][0], aL[i][1], aL[i][2], aL[i][3],
                      aB + 9216u + (uint32_t)i*2304 + (uint32_t)ks*32);
            }
#pragma unroll
            for (int j = 0; j < 4; j++) {
                ldsm4(bH[j][0], bH[j][1], bH[j][2], bH[j][3],
                      bB + (uint32_t)j*2304 + (uint32_t)ks*32);
                ldsm4(bL[j][0], bL[j][1], bL[j][2], bL[j][3],
                      bB + 36864u + (uint32_t)j*2304 + (uint32_t)ks*32);
            }
#pragma unroll
            for (int i = 0; i < 2; i++)
#pragma unroll
                for (int j = 0; j < 4; j++) {
                    mma16816(acc[i][2*j],   aH[i], &bH[j][0]);
                    mma16816(acc[i][2*j+1], aH[i], &bH[j][2]);
                    mma16816(acc[i][2*j],   aH[i], &bL[j][0]);
                    mma16816(acc[i][2*j+1], aH[i], &bL[j][2]);
                    mma16816(acc[i][2*j],   aL[i], &bH[j][0]);
                    mma16816(acc[i][2*j+1], aL[i], &bH[j][2]);
                }
        }
        __syncthreads();
    }

    // ---- epilogue ----
    int tr = lane >> 2, tc = (lane & 3) * 2;
    float2 bb[8];
#pragma unroll
    for (int j = 0; j < 8; j++) {
        int cl = wn + 8*j + tc;
        bb[j].x = __ldg(&bias[cl]);
        bb[j].y = __ldg(&bias[cl+1]);
    }
    if (mode == 0) {
#pragma unroll
        for (int i = 0; i < 2; i++) {
            int r0 = m0 + wm + 16*i + tr;
#pragma unroll
            for (int j = 0; j < 8; j++) {
                int cl = wn + 8*j + tc;
                float2 o0, o1;
                o0.x = acc[i][j][0] + bb[j].x; o0.y = acc[i][j][1] + bb[j].y;
                o1.x = acc[i][j][2] + bb[j].x; o1.y = acc[i][j][3] + bb[j].y;
                *(float2*)&C[r0*256 + cl]     = o0;
                *(float2*)&C[(r0+8)*256 + cl] = o1;
            }
        }
    } else if (mode == 1) {
        float scale = (y == 0) ? RSQRT_DK : 1.f;
        __nv_bfloat16 *iH, *iL;
        if (y == 0)      { iH = g_iQH; iL = g_iQL; }
        else if (y == 1) { iH = g_iKH; iL = g_iKL; }
        else             { iH = g_iVH; iL = g_iVL; }
#pragma unroll
        for (int i = 0; i < 2; i++) {
            int r0 = m0 + wm + 16*i + tr;
            int r1 = r0 + 8;
            int ga0 = r0 / 336, s0 = r0 - ga0*336;
            int ga1 = r1 / 336, s1 = r1 - ga1*336;
#pragma unroll
            for (int j = 0; j < 8; j++) {
                int cl = wn + 8*j + tc;
                int hh = cl >> 5, dd = cl & 31;
                float v0 = (acc[i][j][0] + bb[j].x) * scale;
                float v1 = (acc[i][j][1] + bb[j].y) * scale;
                float v2 = (acc[i][j][2] + bb[j].x) * scale;
                float v3 = (acc[i][j][3] + bb[j].y) * scale;
                __nv_bfloat162 h01 = __floats2bfloat162_rn(v0, v1);
                __nv_bfloat162 h23 = __floats2bfloat162_rn(v2, v3);
                int idx0 = (((ga0 << 3) + hh)*336 + s0)*32 + dd;
                int idx1 = (((ga1 << 3) + hh)*336 + s1)*32 + dd;
                *(uint32_t*)&iH[idx0] = *(uint32_t*)&h01;
                *(uint32_t*)&iL[idx0] = pk_bf2(v0 - __bfloat162float(h01.x),
                                               v1 - __bfloat162float(h01.y));
                *(uint32_t*)&iH[idx1] = *(uint32_t*)&h23;
                *(uint32_t*)&iL[idx1] = pk_bf2(v2 - __bfloat162float(h23.x),
                                               v3 - __bfloat162float(h23.y));
            }
        }
    } else {
        // mode 2: fused residual + LN (and optional second LN), output -> g_E
        float* sRed = (float*)(sm + SMEM_GEMM);
        const int ng = wid >> 1;
        // residual + bias add
#pragma unroll
        for (int i = 0; i < 2; i++) {
            int rg = m0 + wm + 16*i + tr;
#pragma unroll
            for (int j = 0; j < 8; j++) {
                int cl = wn + 8*j + tc;
                float2 e0 = *(const float2*)&g_E[rg*256 + cl];
                float2 e1 = *(const float2*)&g_E[(rg+8)*256 + cl];
                acc[i][j][0] += bb[j].x + e0.x; acc[i][j][1] += bb[j].y + e0.y;
                acc[i][j][2] += bb[j].x + e1.x; acc[i][j][3] += bb[j].y + e1.y;
            }
        }
        int rounds = 1 + dbl;
        for (int rd = 0; rd < rounds; rd++) {
            const float* gv  = rd ? g2v : g1v;
            const float* bv2 = rd ? b2v : b1v;
#pragma unroll
            for (int i = 0; i < 2; i++) {
                float s0 = 0.f, q0 = 0.f, s1 = 0.f, q1 = 0.f;
#pragma unroll
                for (int j = 0; j < 8; j++) {
                    s0 += acc[i][j][0] + acc[i][j][1];
                    q0 += acc[i][j][0]*acc[i][j][0] + acc[i][j][1]*acc[i][j][1];
                    s1 += acc[i][j][2] + acc[i][j][3];
                    q1 += acc[i][j][2]*acc[i][j][2] + acc[i][j][3]*acc[i][j][3];
                }
#pragma unroll
                for (int o = 1; o <= 2; o <<= 1) {
                    s0 += __shfl_xor_sync(0xffffffffu, s0, o);
                    q0 += __shfl_xor_sync(0xffffffffu, q0, o);
                    s1 += __shfl_xor_sync(0xffffffffu, s1, o);
                    q1 += __shfl_xor_sync(0xffffffffu, q1, o);
                }
                if ((lane & 3) == 0) {
                    int r0l = wm + 16*i + tr;
                    sRed[(r0l*4 + ng)*2]         = s0;
                    sRed[(r0l*4 + ng)*2 + 1]     = q0;
                    sRed[((r0l+8)*4 + ng)*2]     = s1;
                    sRed[((r0l+8)*4 + ng)*2 + 1] = q1;
                }
            }
            __syncthreads();
            float mu[2][2], rr[2][2];
#pragma unroll
            for (int i = 0; i < 2; i++) {
                int r0l = wm + 16*i + tr;
                float S0 = 0.f, Q0 = 0.f, S1 = 0.f, Q1 = 0.f;
#pragma unroll
                for (int n = 0; n < 4; n++) {
                    S0 += sRed[(r0l*4 + n)*2];     Q0 += sRed[(r0l*4 + n)*2 + 1];
                    S1 += sRed[((r0l+8)*4 + n)*2]; Q1 += sRed[((r0l+8)*4 + n)*2 + 1];
                }
                mu[i][0] = S0 * (1.f/256.f);
                rr[i][0] = rsqrtf(Q0*(1.f/256.f) - mu[i][0]*mu[i][0] + 1e-5f);
                mu[i][1] = S1 * (1.f/256.f);
                rr[i][1] = rsqrtf(Q1*(1.f/256.f) - mu[i][1]*mu[i][1] + 1e-5f);
            }
            __syncthreads();
#pragma unroll
            for (int i = 0; i < 2; i++)
#pragma unroll
                for (int j = 0; j < 8; j++) {
                    int cl = wn + 8*j + tc;
                    float gg0 = __ldg(&gv[cl]),  gg1 = __ldg(&gv[cl+1]);
                    float bb0 = __ldg(&bv2[cl]), bb1 = __ldg(&bv2[cl+1]);
                    acc[i][j][0] = (acc[i][j][0] - mu[i][0])*rr[i][0]*gg0 + bb0;
                    acc[i][j][1] = (acc[i][j][1] - mu[i][0])*rr[i][0]*gg1 + bb1;
                    acc[i][j][2] = (acc[i][j][2] - mu[i][1])*rr[i][1]*gg0 + bb0;
                    acc[i][j][3] = (acc[i][j][3] - mu[i][1])*rr[i][1]*gg1 + bb1;
                }
        }
#pragma unroll
        for (int i = 0; i < 2; i++) {
            int rg = m0 + wm + 16*i + tr;
#pragma unroll
            for (int j = 0; j < 8; j++) {
                int cl = wn + 8*j + tc;
                float2 o0, o1;
                o0.x = acc[i][j][0]; o0.y = acc[i][j][1];
                o1.x = acc[i][j][2]; o1.y = acc[i][j][3];
                *(float2*)&g_E[rg*256 + cl]     = o0;
                *(float2*)&g_E[(rg+8)*256 + cl] = o1;
            }
        }
    }
}

__global__ void __launch_bounds__(256, 1)
k_tgemm_qkv(const float* __restrict__ bq, const float* __restrict__ bk,
            const float* __restrict__ bv, int mode) {
    extern __shared__ char sm[];
    int y = blockIdx.y;
    const __nv_bfloat16* WH = &g_WtH[y*65536];
    const __nv_bfloat16* WL = &g_WtL[y*65536];
    const float* bias = (y == 0) ? bq : (y == 1) ? bk : bv;
    float* C = (y == 0) ? g_Q : (y == 1) ? g_K : g_V;
    tgemm_body(sm, g_E, WH, WL, bias, C, mode, y,
               nullptr, nullptr, nullptr, nullptr, 0);
}

__global__ void __launch_bounds__(256, 1)
k_wo(const float* __restrict__ bo,
     const float* __restrict__ g1v, const float* __restrict__ b1v,
     const float* __restrict__ g2v, const float* __restrict__ b2v, int dbl) {
    extern __shared__ char sm[];
    tgemm_body(sm, g_O, &g_WtH[3*65536], &g_WtL[3*65536], bo, nullptr, 2, 0,
               g1v, b1v, g2v, b2v, dbl);
}

// ---------------- time attention: tensor-core flash from bf16 images ----------------
#define KT 48
__global__ void __launch_bounds__(256) k_attn_time() {
    __shared__ __nv_bfloat16 sQH[128*40], sQL[128*40];
    __shared__ __nv_bfloat16 sKH[48*40],  sKL[48*40];
    __shared__ __nv_bfloat16 sVH[32*56],  sVL[32*56];

    int g  = blockIdx.z;
    int h  = blockIdx.y;
    int qb = blockIdx.x * 128;
    int tid = threadIdx.x;
    int wid = tid >> 5, lane = tid & 31;
    const int base = ((g*8 + h)*336)*32;

    uint32_t uQH = smem_u32(sQH), uQL = smem_u32(sQL);
    uint32_t uKH = smem_u32(sKH), uKL = smem_u32(sKL);
    uint32_t uVH = smem_u32(sVH), uVL = smem_u32(sVL);

    // stage Q (pure copies — already bf16 hi/lo, pre-scaled)
#pragma unroll
    for (int i = 0; i < 2; i++) {
        int idx = tid + 256*i;          // 512
        int r = idx >> 2, q = idx & 3;
        int qi = qb + r; if (qi > 335) qi = 335;
        *(uint4*)&sQH[r*40 + q*8] = *(const uint4*)&g_iQH[base + qi*32 + q*8];
        *(uint4*)&sQL[r*40 + q*8] = *(const uint4*)&g_iQL[base + qi*32 + q*8];
    }
    __syncthreads();

    uint32_t aQoff = (uint32_t)(wid*16 + (lane & 7) + ((lane >> 3) & 1)*8)*80
                   + ((lane >> 4) & 1)*16;
    uint32_t qH[2][4], qL[2][4];
#pragma unroll
    for (int ks = 0; ks < 2; ks++) {
        ldsm4(qH[ks][0], qH[ks][1], qH[ks][2], qH[ks][3], uQH + aQoff + ks*32);
        ldsm4(qL[ks][0], qL[ks][1], qL[ks][2], qL[ks][3], uQL + aQoff + ks*32);
    }

    float o[4][4];
#pragma unroll
    for (int j = 0; j < 4; j++)
#pragma unroll
        for (int q = 0; q < 4; q++) o[j][q] = 0.f;
    float m0 = -1e30f, m1 = -1e30f, sum0 = 0.f, sum1 = 0.f;

    uint32_t kOff = (uint32_t)((lane & 7) + ((lane >> 4) & 1)*8)*80 + ((lane >> 3) & 1)*16;
    uint32_t vOff = (uint32_t)((lane & 7) + ((lane >> 4) & 1)*8)*112 + ((lane >> 3) & 1)*16;

    // stage K/V tile 0 (copies + V transpose)
#pragma unroll
    for (int i = 0; i < 6; i++) {
        int p = tid + 256*i;            // 0..1535
        int img = p >= 768;
        int q = img ? (p - 768) : p;
        int r = q >> 4, c2 = (q & 15)*2;
        const __nv_bfloat16* ks = img ? g_iKL : g_iKH;
        *(uint32_t*)&((img ? sKL : sKH)[r*40 + c2]) =
            *(const uint32_t*)&ks[base + r*32 + c2];
        const __nv_bfloat16* vs = img ? g_iVL : g_iVH;
        uint32_t vv = *(const uint32_t*)&vs[base + r*32 + c2];
        __nv_bfloat162 pv = *(__nv_bfloat162*)&vv;
        __nv_bfloat16* vd = img ? sVL : sVH;
        vd[c2*56 + r]     = pv.x;
        vd[(c2+1)*56 + r] = pv.y;
    }
    __syncthreads();

    uint32_t pK[6], pV[6];
    for (int kt = 0; kt < 7; kt++) {
        if (kt < 6) {
            int kb = (kt + 1)*KT;
#pragma unroll
            for (int i = 0; i < 6; i++) {
                int p = tid + 256*i;
                int img = p >= 768;
                int q = img ? (p - 768) : p;
                int r = q >> 4, c2 = (q & 15)*2;
                pK[i] = *(const uint32_t*)&((img ? g_iKL : g_iKH)[base + (kb + r)*32 + c2]);
                pV[i] = *(const uint32_t*)&((img ? g_iVL : g_iVH)[base + (kb + r)*32 + c2]);
            }
        }

        // scores S (16 x 48) = Q K^T, 3-term bf16 split
        float sc[6][4];
#pragma unroll
        for (int j = 0; j < 6; j++)
#pragma unroll
            for (int q = 0; q < 4; q++) sc[j][q] = 0.f;
#pragma unroll
        for (int ks = 0; ks < 2; ks++) {
#pragma unroll
            for (int ng = 0; ng < 3; ng++) {
                uint32_t bH[4], bL[4];
                ldsm4(bH[0], bH[1], bH[2], bH[3], uKH + kOff + ng*(16*80) + ks*32);
                ldsm4(bL[0], bL[1], bL[2], bL[3], uKL + kOff + ng*(16*80) + ks*32);
                mma16816(sc[2*ng],   qH[ks], &bH[0]);
                mma16816(sc[2*ng+1], qH[ks], &bH[2]);
                mma16816(sc[2*ng],   qH[ks], &bL[0]);
                mma16816(sc[2*ng+1], qH[ks], &bL[2]);
                mma16816(sc[2*ng],   qL[ks], &bH[0]);
                mma16816(sc[2*ng+1], qL[ks], &bH[2]);
            }
        }

        // online softmax
        float t0 = -1e30f, t1 = -1e30f;
#pragma unroll
        for (int j = 0; j < 6; j++) {
            t0 = fmaxf(t0, fmaxf(sc[j][0], sc[j][1]));
            t1 = fmaxf(t1, fmaxf(sc[j][2], sc[j][3]));
        }
        t0 = fmaxf(t0, __shfl_xor_sync(0xffffffffu, t0, 1));
        t0 = fmaxf(t0, __shfl_xor_sync(0xffffffffu, t0, 2));
        t1 = fmaxf(t1, __shfl_xor_sync(0xffffffffu, t1, 1));
        t1 = fmaxf(t1, __shfl_xor_sync(0xffffffffu, t1, 2));
        float nm0 = fmaxf(m0, t0), nm1 = fmaxf(m1, t1);
        float c0 = __expf(m0 - nm0), c1 = __expf(m1 - nm1);
        float ts0 = 0.f, ts1 = 0.f;
#pragma unroll
        for (int j = 0; j < 6; j++) {
            sc[j][0] = __expf(sc[j][0] - nm0);
            sc[j][1] = __expf(sc[j][1] - nm0);
            sc[j][2] = __expf(sc[j][2] - nm1);
            sc[j][3] = __expf(sc[j][3] - nm1);
            ts0 += sc[j][0] + sc[j][1];
            ts1 += sc[j][2] + sc[j][3];
        }
        sum0 = sum0*c0 + ts0;
        sum1 = sum1*c1 + ts1;
#pragma unroll
        for (int j = 0; j < 4; j++) {
            o[j][0] *= c0; o[j][1] *= c0; o[j][2] *= c1; o[j][3] *= c1;
        }
        m0 = nm0; m1 = nm1;

        // PV, 3-term split
#pragma unroll
        for (int kb = 0; kb < 3; kb++) {
            uint32_t aP[4], aR[4];
#pragma unroll
            for (int t = 0; t < 2; t++) {
                int j = 2*kb + t;
                float x0 = sc[j][0], x1 = sc[j][1], x2 = sc[j][2], x3 = sc[j][3];
                __nv_bfloat162 h01 = __floats2bfloat162_rn(x0, x1);
                __nv_bfloat162 h23 = __floats2bfloat162_rn(x2, x3);
                aP[2*t]   = *(uint32_t*)&h01;
                aP[2*t+1] = *(uint32_t*)&h23;
                aR[2*t]   = pk_bf2(x0 - __bfloat162float(h01.x),
                                   x1 - __bfloat162float(h01.y));
                aR[2*t+1] = pk_bf2(x2 - __bfloat162float(h23.x),
                                   x3 - __bfloat162float(h23.y));
            }
#pragma unroll
            for (int ng = 0; ng < 2; ng++) {
                uint32_t vH[4], vL[4];
                ldsm4(vH[0], vH[1], vH[2], vH[3], uVH + vOff + ng*(16*112) + kb*32);
                ldsm4(vL[0], vL[1], vL[2], vL[3], uVL + vOff + ng*(16*112) + kb*32);
                mma16816(o[2*ng],   aP, &vH[0]);
                mma16816(o[2*ng+1], aP, &vH[2]);
                mma16816(o[2*ng],   aP, &vL[0]);
                mma16816(o[2*ng+1], aP, &vL[2]);
                mma16816(o[2*ng],   aR, &vH[0]);
                mma16816(o[2*ng+1], aR, &vH[2]);
            }
        }
        __syncthreads();
        if (kt < 6) {
#pragma unroll
            for (int i = 0; i < 6; i++) {
                int p = tid + 256*i;
                int img = p >= 768;
                int q = img ? (p - 768) : p;
                int r = q >> 4, c2 = (q & 15)*2;
                *(uint32_t*)&((img ? sKL : sKH)[r*40 + c2]) = pK[i];
                __nv_bfloat162 pv = *(__nv_bfloat162*)&pV[i];
                __nv_bfloat16* vd = img ? sVL : sVH;
                vd[c2*56 + r]     = pv.x;
                vd[(c2+1)*56 + r] = pv.y;
            }
            __syncthreads();
        }
    }

    // finalize
    sum0 += __shfl_xor_sync(0xffffffffu, sum0, 1);
    sum0 += __shfl_xor_sync(0xffffffffu, sum0, 2);
    sum1 += __shfl_xor_sync(0xffffffffu, sum1, 1);
    sum1 += __shfl_xor_sync(0xffffffffu, sum1, 2);
    float inv0 = 1.f / sum0, inv1 = 1.f / sum1;
    int q0 = qb + wid*16 + (lane >> 2);
    int q1 = q0 + 8;
    int cbase = h*32 + 2*(lane & 3);
#pragma unroll
    for (int j = 0; j < 4; j++) {
        int col = cbase + 8*j;
        if (q0 < 336) {
            float2 w0; w0.x = o[j][0]*inv0; w0.y = o[j][1]*inv0;
            *(float2*)&g_O[(g*SS + q0)*DD + col] = w0;
        }
        if (q1 < 336) {
            float2 w1; w1.x = o[j][2]*inv1; w1.y = o[j][3]*inv1;
            *(float2*)&g_O[(g*SS + q1)*DD + col] = w1;
        }
    }
}

// ---------------- variable attention (L=8, fp32 path) ----------------
__global__ void __launch_bounds__(64) k_attn_var() {
    __shared__ __align__(16) float Ks[8][256];
    __shared__ __align__(16) float Vs[8][256];

    int bs = blockIdx.x;
    int b = bs / SS;
    int s = bs - b*SS;
    int tid = threadIdx.x;

#pragma unroll
    for (int i = 0; i < 8; i++) {
        int f = tid + 64*i;
        int v = f >> 6;
        int dq = f & 63;
        int ga = ((b*VV + v)*SS + s)*DD + dq*4;
        *(float4*)&Ks[v][dq*4] = *(const float4*)&g_K[ga];
        *(float4*)&Vs[v][dq*4] = *(const float4*)&g_V[ga];
    }
    __syncthreads();

    int qv = tid & 7;
    int h  = tid >> 3;
    const float* qp = &g_Q[((b*VV + qv)*SS + s)*DD + h*32];
    float q[32];
#pragma unroll
    for (int i = 0; i < 8; i++) {
        float4 v4 = *(const float4*)&qp[i*4];
        q[i*4+0] = v4.x; q[i*4+1] = v4.y; q[i*4+2] = v4.z; q[i*4+3] = v4.w;
    }
    float sc[8];
    float mx = -1e30f;
#pragma unroll
    for (int v = 0; v < 8; v++) {
        float t = 0.f;
#pragma unroll
        for (int d = 0; d < 32; d++) t += q[d]*Ks[v][h*32 + d];
        t *= RSQRT_DK;
        sc[v] = t;
        mx = fmaxf(mx, t);
    }
    float sum = 0.f;
#pragma unroll
    for (int v = 0; v < 8; v++) { sc[v] = __expf(sc[v] - mx); sum += sc[v]; }
    float inv = 1.f / sum;

    float o[32];
#pragma unroll
    for (int d = 0; d < 32; d++) o[d] = 0.f;
#pragma unroll
    for (int v = 0; v < 8; v++)
#pragma unroll
        for (int d = 0; d < 32; d++) o[d] += sc[v]*Vs[v][h*32 + d];

    float* op = &g_O[((b*VV + qv)*SS + s)*DD + h*32];
#pragma unroll
    for (int i = 0; i < 8; i++) {
        float4 v4;
        v4.x = o[i*4+0]*inv; v4.y = o[i*4+1]*inv;
        v4.z = o[i*4+2]*inv; v4.w = o[i*4+3]*inv;
        *(float4*)&op[i*4] = v4;
    }
}

// ---------------- final projection ----------------
__global__ void k_out_init(const float* __restrict__ pb, float* __restrict__ out) {
    int i = blockIdx.x*256 + threadIdx.x;
    if (i < BB*PP*VV) {
        int p = (i % (PP*VV)) >> 3;
        out[i] = pb[p];
    }
}

__global__ void __launch_bounds__(256) k_proj(const float* __restrict__ W,
                                              float* __restrict__ out) {
    __shared__ float Ws[64][96];
    __shared__ float Es[16][64];
    int k0 = blockIdx.x * 512;
    int tid = threadIdx.x;

    float acc[6];
    const float* erow[6];
    int wcol[6], oidx[6];
#pragma unroll
    for (int i = 0; i < 6; i++) {
        int qq = tid + 256*i;
        int bv = qq / 96;
        int p  = qq - bv*96;
        acc[i] = 0.f;
        erow[i] = &Es[bv][0];
        wcol[i] = p;
        oidx[i] = (bv >> 3)*(PP*VV) + p*VV + (bv & 7);
    }

    for (int kt = 0; kt < 8; kt++) {
        int kb = k0 + kt*64;
        __syncthreads();
#pragma unroll
        for (int i = 0; i < 6; i++) {
            int f = tid + 256*i;
            int kk = f / 24;
            int pq = f - kk*24;
            *(float4*)&Ws[kk][pq*4] = *(const float4*)&W[(kb + kk)*PP + pq*4];
        }
        {
            int bv = tid >> 4;
            int kq = tid & 15;
            *(float4*)&Es[bv][kq*4] = *(const float4*)&g_E[bv*SD + kb + kq*4];
        }
        __syncthreads();
        for (int kk = 0; kk < 64; kk++) {
#pragma unroll
            for (int i = 0; i < 6; i++)
                acc[i] += erow[i][kk] * Ws[kk][wcol[i]];
        }
    }
#pragma unroll
    for (int i = 0; i < 6; i++)
        atomicAdd(&out[oidx[i]], acc[i]);
}

// ---------------- launch ----------------
extern "C" void kernel_launch(void* const* d_in, const int* in_sizes, int n_in,
                              void* d_out, int out_size) {
    const float* x      = (const float*)d_in[0];
    const float* emb_w  = (const float*)d_in[1];
    const float* emb_b  = (const float*)d_in[2];
    const float* Wq     = (const float*)d_in[3];
    const float* bq     = (const float*)d_in[4];
    const float* Wk     = (const float*)d_in[5];
    const float* bk     = (const float*)d_in[6];
    const float* Wv     = (const float*)d_in[7];
    const float* bv     = (const float*)d_in[8];
    const float* Wo     = (const float*)d_in[9];
    const float* bo     = (const float*)d_in[10];
    const float* ln1_g  = (const float*)d_in[11];
    const float* ln1_b  = (const float*)d_in[12];
    const float* norm_g = (const float*)d_in[13];
    const float* norm_b = (const float*)d_in[14];
    const float* proj_w = (const float*)d_in[15];
    const float* proj_b = (const float*)d_in[16];
    float* out = (float*)d_out;

    cudaFuncSetAttribute(k_tgemm_qkv, cudaFuncAttributeMaxDynamicSharedMemorySize, SMEM_GEMM);
    cudaFuncSetAttribute(k_wo,        cudaFuncAttributeMaxDynamicSharedMemorySize, SMEM_WO);

    k_prep<<<dim3(256, 4), 256>>>(Wq, Wk, Wv, Wo);
    k_embed<<<NT, 256>>>(x, emb_w, emb_b);

    for (int it = 0; it < 10; it++) {
        // phase A: attention over time axis (bf16 image path)
        k_tgemm_qkv<<<dim3(84, 3), 256, SMEM_GEMM>>>(bq, bk, bv, 1);
        k_attn_time<<<dim3(3, 8, 16), 256>>>();
        k_wo<<<84, 256, SMEM_WO>>>(bo, ln1_g, ln1_b, norm_g, norm_b, 1);
        // phase B: attention over variable axis (fp32 path)
        k_tgemm_qkv<<<dim3(84, 3), 256, SMEM_GEMM>>>(bq, bk, bv, 0);
        k_attn_var<<<BB*SS, 64>>>();
        k_wo<<<84, 256, SMEM_WO>>>(bo, ln1_g, ln1_b, norm_g, norm_b, 0);
    }

    k_out_init<<<6, 256>>>(proj_b, out);
    k_proj<<<SD/512, 256>>>(proj_w, out);
}

// round 13
// speedup vs baseline: 1.1058x; 1.0336x over previous
#include <cuda_runtime.h>
#include <cuda_bf16.h>
#include <math.h>
#include <stdint.h>

// ---------------- problem constants ----------------
#define BB   2
#define SS   336
#define VV   8
#define DD   256
#define HH   8
#define DK   32
#define PP   96
#define NT   (BB*VV*SS)      // 5376 tokens
#define SD   (SS*DD)         // 86016
#define RSQRT_DK 0.17677669529663687f   // 1/sqrt(32)

// ---------------- scratch ----------------
__device__ float g_E[NT*DD];
__device__ float g_Q[NT*DD];
__device__ float g_K[NT*DD];
__device__ float g_V[NT*DD];
__device__ float g_O[NT*DD];
// transposed bf16 weight images W^T[n][k], hi/lo split: [w(4)][256][256]
__device__ __align__(16) __nv_bfloat16 g_WtH[4*65536];
__device__ __align__(16) __nv_bfloat16 g_WtL[4*65536];
// phase-A QKV bf16 images: [(g*8+h)*336 + s]*32 + d  (Q pre-scaled by 1/sqrt(dk))
#define IMG_ELEMS (128*336*32)
__device__ __align__(16) __nv_bfloat16 g_iQH[IMG_ELEMS], g_iQL[IMG_ELEMS];
__device__ __align__(16) __nv_bfloat16 g_iKH[IMG_ELEMS], g_iKL[IMG_ELEMS];
__device__ __align__(16) __nv_bfloat16 g_iVH[IMG_ELEMS], g_iVL[IMG_ELEMS];

// ---------------- helpers ----------------
__device__ __forceinline__ uint32_t smem_u32(const void* p) {
    uint32_t a;
    asm("{ .reg .u64 t; cvta.to.shared.u64 t, %1; cvt.u32.u64 %0, t; }" : "=r"(a) : "l"(p));
    return a;
}
__device__ __forceinline__ void ldsm4(uint32_t& r0, uint32_t& r1, uint32_t& r2, uint32_t& r3,
                                      uint32_t a) {
    asm volatile("ldmatrix.sync.aligned.m8n8.x4.shared.b16 {%0,%1,%2,%3}, [%4];"
        : "=r"(r0), "=r"(r1), "=r"(r2), "=r"(r3) : "r"(a));
}
__device__ __forceinline__ void mma16816(float* c, const uint32_t* a, const uint32_t* b) {
    asm volatile("mma.sync.aligned.m16n8k16.row.col.f32.bf16.bf16.f32 "
        "{%0,%1,%2,%3}, {%4,%5,%6,%7}, {%8,%9}, {%0,%1,%2,%3};"
        : "+f"(c[0]), "+f"(c[1]), "+f"(c[2]), "+f"(c[3])
        : "r"(a[0]), "r"(a[1]), "r"(a[2]), "r"(a[3]), "r"(b[0]), "r"(b[1]));
}
__device__ __forceinline__ void cpa16(uint32_t dst, const void* src) {
    asm volatile("cp.async.cg.shared.global [%0], [%1], 16;" :: "r"(dst), "l"(src));
}
#define CPA_COMMIT() asm volatile("cp.async.commit_group;" ::: "memory")
#define CPA_WAIT0()  asm volatile("cp.async.wait_group 0;" ::: "memory")

__device__ __forceinline__ uint32_t pk_bf2(float lo, float hi) {
    __nv_bfloat162 h = __floats2bfloat162_rn(lo, hi);
    return *(uint32_t*)&h;
}

// ---------------- embed ----------------
__global__ void k_embed(const float* __restrict__ x,
                        const float* __restrict__ ew,
                        const float* __restrict__ eb) {
    int idx = blockIdx.x * 256 + threadIdx.x;
    int d = idx & 255;
    int t = idx >> 8;
    int b = t / (VV*SS);
    int r = t - b*(VV*SS);
    int v = r / SS;
    int s = r - v*SS;
    g_E[idx] = x[(b*SS + s)*VV + v] * ew[d] + eb[d];
}

// ---------------- weight prep: W^T + bf16 hi/lo split ----------------
__global__ void k_prep(const float* __restrict__ Wq, const float* __restrict__ Wk,
                       const float* __restrict__ Wv, const float* __restrict__ Wo) {
    int e = blockIdx.x * 256 + threadIdx.x;   // 0..65535
    int w = blockIdx.y;
    int n = e >> 8, k = e & 255;
    const float* W = (w == 0) ? Wq : (w == 1) ? Wk : (w == 2) ? Wv : Wo;
    float a = W[k*256 + n];
    __nv_bfloat16 h = __float2bfloat16(a);
    __nv_bfloat16 l = __float2bfloat16(a - __bfloat162float(h));
    g_WtH[w*65536 + n*256 + k] = h;
    g_WtL[w*65536 + n*256 + k] = l;
}

// ---------------- pipelined mma.sync bf16x3 GEMM (templated tile) ----------------
// TM rows x 256 cols, TM*4 threads, warp tile 32x64, K-chunks of 64,
// double-buffered + cp.async.
// MODE 0: C = A@W + bias (fp32 out)
// MODE 1: QKV phase-A image epilogue (bf16 hi/lo images, Q pre-scaled)
// MODE 2: Wo epilogue: residual(g_E) + bias, LN (optional second LN), out g_E
#define SMEM_T(TM)  ((TM)*576 + 147456)
#define SMEM_WO     (SMEM_T(64) + 2048)

template<int TM, int MODE>
__device__ __forceinline__ void tgemm_body(char* sm, const float* __restrict__ A,
                                           const __nv_bfloat16* __restrict__ WtH,
                                           const __nv_bfloat16* __restrict__ WtL,
                                           const float* __restrict__ bias,
                                           float* __restrict__ C, int y,
                                           const float* g1v, const float* b1v,
                                           const float* g2v, const float* b2v, int dbl) {
    constexpr int NTHR = TM*4;
    constexpr int MW   = TM/32;              // warps along M
    constexpr int A_SPL = TM*144;            // one A split (rows*pitch)
    constexpr int A_BUF = 2*A_SPL;
    constexpr int GB0   = 2*A_BUF;           // B region start
    constexpr int B_ITERS = 2048/NTHR;
    const int tid = threadIdx.x;
    const int wid = tid >> 5, lane = tid & 31;
    const int m0 = blockIdx.x * TM;
    const int wm = (wid % MW) * 32;
    const int wn = (wid / MW) * 64;
    uint32_t sb = smem_u32(sm);

    float acc[2][8][4];
#pragma unroll
    for (int i = 0; i < 2; i++)
#pragma unroll
        for (int j = 0; j < 8; j++)
#pragma unroll
            for (int q = 0; q < 4; q++) acc[i][j][q] = 0.f;

    uint32_t aRow = wm + (lane & 7) + ((lane >> 3) & 1) * 8;
    uint32_t aOff = aRow*144 + ((lane >> 4) & 1)*16;
    uint32_t bRow = wn + (lane & 7) + ((lane >> 4) & 1) * 8;
    uint32_t bOff = bRow*144 + ((lane >> 3) & 1)*16;

    // prologue: A chunk0 -> regs, B chunk0 -> cp.async buf0
    float4 av[4];
    {
        const float4* Ag = (const float4*)(A + m0*256);
#pragma unroll
        for (int i = 0; i < 4; i++) {
            int f = tid + NTHR*i;
            av[i] = Ag[(f >> 4)*64 + (f & 15)];
        }
#pragma unroll
        for (int i = 0; i < B_ITERS; i++) {
            int f = tid + NTHR*i;
            int r = f >> 3, q = f & 7;
            uint32_t off = (uint32_t)r*144 + (uint32_t)q*16;
            cpa16(sb + GB0 + off, WtH + (r << 8) + q*8);
            cpa16(sb + GB0 + 36864 + off, WtL + (r << 8) + q*8);
        }
        CPA_COMMIT();
    }

#pragma unroll
    for (int kc = 0; kc < 4; kc++) {
        int buf = kc & 1;
        uint32_t gaB = buf*A_BUF;
        uint32_t gbB = GB0 + buf*73728;
#pragma unroll
        for (int i = 0; i < 4; i++) {
            int f = tid + NTHR*i;
            int r = f >> 4, q = f & 15;
            float4 v = av[i];
            __nv_bfloat16 h0 = __float2bfloat16(v.x);
            __nv_bfloat16 h1 = __float2bfloat16(v.y);
            __nv_bfloat16 h2 = __float2bfloat16(v.z);
            __nv_bfloat16 h3 = __float2bfloat16(v.w);
            __nv_bfloat16 l0 = __float2bfloat16(v.x - __bfloat162float(h0));
            __nv_bfloat16 l1 = __float2bfloat16(v.y - __bfloat162float(h1));
            __nv_bfloat16 l2 = __float2bfloat16(v.z - __bfloat162float(h2));
            __nv_bfloat16 l3 = __float2bfloat16(v.w - __bfloat162float(h3));
            uint2 hp, lp;
            hp.x = (uint32_t)__bfloat16_as_ushort(h0) | ((uint32_t)__bfloat16_as_ushort(h1) << 16);
            hp.y = (uint32_t)__bfloat16_as_ushort(h2) | ((uint32_t)__bfloat16_as_ushort(h3) << 16);
            lp.x = (uint32_t)__bfloat16_as_ushort(l0) | ((uint32_t)__bfloat16_as_ushort(l1) << 16);
            lp.y = (uint32_t)__bfloat16_as_ushort(l2) | ((uint32_t)__bfloat16_as_ushort(l3) << 16);
            uint32_t off = (uint32_t)r*144 + (uint32_t)q*8;
            *(uint2*)(sm + gaB + off)         = hp;
            *(uint2*)(sm + gaB + A_SPL + off) = lp;
        }
        CPA_WAIT0();
        __syncthreads();

        if (kc < 3) {
            const float4* Ag = (const float4*)(A + m0*256 + (kc + 1)*64);
#pragma unroll
            for (int i = 0; i < 4; i++) {
                int f = tid + NTHR*i;
                av[i] = Ag[(f >> 4)*64 + (f & 15)];
            }
            uint32_t gbN = GB0 + (buf ^ 1)*73728;
#pragma unroll
            for (int i = 0; i < B_ITERS; i++) {
                int f = tid + NTHR*i;
                int r = f >> 3, q = f & 7;
                uint32_t off = (uint32_t)r*144 + (uint32_t)q*16;
                cpa16(sb + gbN + off, WtH + (r << 8) + (kc + 1)*64 + q*8);
                cpa16(sb + gbN + 36864 + off, WtL + (r << 8) + (kc + 1)*64 + q*8);
            }
            CPA_COMMIT();
        }

        uint32_t aB = sb + gaB + aOff;
        uint32_t bB = sb + gbB + bOff;
#pragma unroll
        for (int ks = 0; ks < 4; ks++) {
            uint32_t aH[2][4], aL[2][4], bH[4][4], bL[4][4];
#pragma unroll
            for (int i = 0; i < 2; i++) {
                ldsm4(aH[i][0], aH[i][1], aH[i][2], aH[i][3],
                      aB + (uint32_t)i*2304 + (uint32_t)ks*32);
                ldsm4(aL[i][0], aL[i][1], aL[i][2], aL[i][3],
                      aB + (uint32_t)A_SPL + (uint32_t)i*2304 + (uint32_t)ks*32);
            }
#pragma unroll
            for (int j = 0; j < 4; j++) {
                ldsm4(bH[j][0], bH[j][1], bH[j][2], bH[j][3],
                      bB + (uint32_t)j*2304 + (uint32_t)ks*32);
                ldsm4(bL[j][0], bL[j][1], bL[j][2], bL[j][3],
                      bB + 36864u + (uint32_t)j*2304 + (uint32_t)ks*32);
            }
#pragma unroll
            for (int i = 0; i < 2; i++)
#pragma unroll
                for (int j = 0; j < 4; j++) {
                    mma16816(acc[i][2*j],   aH[i], &bH[j][0]);
                    mma16816(acc[i][2*j+1], aH[i], &bH[j][2]);
                    mma16816(acc[i][2*j],   aH[i], &bL[j][0]);
                    mma16816(acc[i][2*j+1], aH[i], &bL[j][2]);
                    mma16816(acc[i][2*j],   aL[i], &bH[j][0]);
                    mma16816(acc[i][2*j+1], aL[i], &bH[j][2]);
                }
        }
        __syncthreads();
    }

    // ---- epilogue ----
    int tr = lane >> 2, tc = (lane & 3) * 2;
    float2 bb[8];
#pragma unroll
    for (int j = 0; j < 8; j++) {
        int cl = wn + 8*j + tc;
        bb[j].x = __ldg(&bias[cl]);
        bb[j].y = __ldg(&bias[cl+1]);
    }
    if (MODE == 0) {
#pragma unroll
        for (int i = 0; i < 2; i++) {
            int r0 = m0 + wm + 16*i + tr;
#pragma unroll
            for (int j = 0; j < 8; j++) {
                int cl = wn + 8*j + tc;
                float2 o0, o1;
                o0.x = acc[i][j][0] + bb[j].x; o0.y = acc[i][j][1] + bb[j].y;
                o1.x = acc[i][j][2] + bb[j].x; o1.y = acc[i][j][3] + bb[j].y;
                *(float2*)&C[r0*256 + cl]     = o0;
                *(float2*)&C[(r0+8)*256 + cl] = o1;
            }
        }
    } else if (MODE == 1) {
        float scale = (y == 0) ? RSQRT_DK : 1.f;
        __nv_bfloat16 *iH, *iL;
        if (y == 0)      { iH = g_iQH; iL = g_iQL; }
        else if (y == 1) { iH = g_iKH; iL = g_iKL; }
        else             { iH = g_iVH; iL = g_iVL; }
#pragma unroll
        for (int i = 0; i < 2; i++) {
            int r0 = m0 + wm + 16*i + tr;
            int r1 = r0 + 8;
            int ga0 = r0 / 336, s0 = r0 - ga0*336;
            int ga1 = r1 / 336, s1 = r1 - ga1*336;
#pragma unroll
            for (int j = 0; j < 8; j++) {
                int cl = wn + 8*j + tc;
                int hh = cl >> 5, dd = cl & 31;
                float v0 = (acc[i][j][0] + bb[j].x) * scale;
                float v1 = (acc[i][j][1] + bb[j].y) * scale;
                float v2 = (acc[i][j][2] + bb[j].x) * scale;
                float v3 = (acc[i][j][3] + bb[j].y) * scale;
                __nv_bfloat162 h01 = __floats2bfloat162_rn(v0, v1);
                __nv_bfloat162 h23 = __floats2bfloat162_rn(v2, v3);
                int idx0 = (((ga0 << 3) + hh)*336 + s0)*32 + dd;
                int idx1 = (((ga1 << 3) + hh)*336 + s1)*32 + dd;
                *(uint32_t*)&iH[idx0] = *(uint32_t*)&h01;
                *(uint32_t*)&iL[idx0] = pk_bf2(v0 - __bfloat162float(h01.x),
                                               v1 - __bfloat162float(h01.y));
                *(uint32_t*)&iH[idx1] = *(uint32_t*)&h23;
                *(uint32_t*)&iL[idx1] = pk_bf2(v2 - __bfloat162float(h23.x),
                                               v3 - __bfloat162float(h23.y));
            }
        }
    } else {
        // MODE 2: fused residual + LN (and optional second LN), output -> g_E
        float* sRed = (float*)(sm + SMEM_T(64));
        const int ng = wid / MW;
#pragma unroll
        for (int i = 0; i < 2; i++) {
            int rg = m0 + wm + 16*i + tr;
#pragma unroll
            for (int j = 0; j < 8; j++) {
                int cl = wn + 8*j + tc;
                float2 e0 = *(const float2*)&g_E[rg*256 + cl];
                float2 e1 = *(const float2*)&g_E[(rg+8)*256 + cl];
                acc[i][j][0] += bb[j].x + e0.x; acc[i][j][1] += bb[j].y + e0.y;
                acc[i][j][2] += bb[j].x + e1.x; acc[i][j][3] += bb[j].y + e1.y;
            }
        }
        int rounds = 1 + dbl;
        for (int rd = 0; rd < rounds; rd++) {
            const float* gv  = rd ? g2v : g1v;
            const float* bv2 = rd ? b2v : b1v;
#pragma unroll
            for (int i = 0; i < 2; i++) {
                float s0 = 0.f, q0 = 0.f, s1 = 0.f, q1 = 0.f;
#pragma unroll
                for (int j = 0; j < 8; j++) {
                    s0 += acc[i][j][0] + acc[i][j][1];
                    q0 += acc[i][j][0]*acc[i][j][0] + acc[i][j][1]*acc[i][j][1];
                    s1 += acc[i][j][2] + acc[i][j][3];
                    q1 += acc[i][j][2]*acc[i][j][2] + acc[i][j][3]*acc[i][j][3];
                }
#pragma unroll
                for (int o = 1; o <= 2; o <<= 1) {
                    s0 += __shfl_xor_sync(0xffffffffu, s0, o);
                    q0 += __shfl_xor_sync(0xffffffffu, q0, o);
                    s1 += __shfl_xor_sync(0xffffffffu, s1, o);
                    q1 += __shfl_xor_sync(0xffffffffu, q1, o);
                }
                if ((lane & 3) == 0) {
                    int r0l = wm + 16*i + tr;
                    sRed[(r0l*4 + ng)*2]         = s0;
                    sRed[(r0l*4 + ng)*2 + 1]     = q0;
                    sRed[((r0l+8)*4 + ng)*2]     = s1;
                    sRed[((r0l+8)*4 + ng)*2 + 1] = q1;
                }
            }
            __syncthreads();
            float mu[2][2], rr[2][2];
#pragma unroll
            for (int i = 0; i < 2; i++) {
                int r0l = wm + 16*i + tr;
                float S0 = 0.f, Q0 = 0.f, S1 = 0.f, Q1 = 0.f;
#pragma unroll
                for (int n = 0; n < 4; n++) {
                    S0 += sRed[(r0l*4 + n)*2];     Q0 += sRed[(r0l*4 + n)*2 + 1];
                    S1 += sRed[((r0l+8)*4 + n)*2]; Q1 += sRed[((r0l+8)*4 + n)*2 + 1];
                }
                mu[i][0] = S0 * (1.f/256.f);
                rr[i][0] = rsqrtf(Q0*(1.f/256.f) - mu[i][0]*mu[i][0] + 1e-5f);
                mu[i][1] = S1 * (1.f/256.f);
                rr[i][1] = rsqrtf(Q1*(1.f/256.f) - mu[i][1]*mu[i][1] + 1e-5f);
            }
            __syncthreads();
#pragma unroll
            for (int i = 0; i < 2; i++)
#pragma unroll
                for (int j = 0; j < 8; j++) {
                    int cl = wn + 8*j + tc;
                    float gg0 = __ldg(&gv[cl]),  gg1 = __ldg(&gv[cl+1]);
                    float bb0 = __ldg(&bv2[cl]), bb1 = __ldg(&bv2[cl+1]);
                    acc[i][j][0] = (acc[i][j][0] - mu[i][0])*rr[i][0]*gg0 + bb0;
                    acc[i][j][1] = (acc[i][j][1] - mu[i][0])*rr[i][0]*gg1 + bb1;
                    acc[i][j][2] = (acc[i][j][2] - mu[i][1])*rr[i][1]*gg0 + bb0;
                    acc[i][j][3] = (acc[i][j][3] - mu[i][1])*rr[i][1]*gg1 + bb1;
                }
        }
#pragma unroll
        for (int i = 0; i < 2; i++) {
            int rg = m0 + wm + 16*i + tr;
#pragma unroll
            for (int j = 0; j < 8; j++) {
                int cl = wn + 8*j + tc;
                float2 o0, o1;
                o0.x = acc[i][j][0]; o0.y = acc[i][j][1];
                o1.x = acc[i][j][2]; o1.y = acc[i][j][3];
                *(float2*)&g_E[rg*256 + cl]     = o0;
                *(float2*)&g_E[(rg+8)*256 + cl] = o1;
            }
        }
    }
}

__global__ void __launch_bounds__(512, 1)
k_tgemm_qkv_img(const float* __restrict__ bq, const float* __restrict__ bk,
                const float* __restrict__ bv) {
    extern __shared__ char sm[];
    int y = blockIdx.y;
    tgemm_body<128, 1>(sm, g_E, &g_WtH[y*65536], &g_WtL[y*65536],
                       (y == 0) ? bq : (y == 1) ? bk : bv, nullptr, y,
                       nullptr, nullptr, nullptr, nullptr, 0);
}

__global__ void __launch_bounds__(512, 1)
k_tgemm_qkv_f32(const float* __restrict__ bq, const float* __restrict__ bk,
                const float* __restrict__ bv) {
    extern __shared__ char sm[];
    int y = blockIdx.y;
    float* C = (y == 0) ? g_Q : (y == 1) ? g_K : g_V;
    tgemm_body<128, 0>(sm, g_E, &g_WtH[y*65536], &g_WtL[y*65536],
                       (y == 0) ? bq : (y == 1) ? bk : bv, C, y,
                       nullptr, nullptr, nullptr, nullptr, 0);
}

__global__ void __launch_bounds__(256, 1)
k_wo(const float* __restrict__ bo,
     const float* __restrict__ g1v, const float* __restrict__ b1v,
     const float* __restrict__ g2v, const float* __restrict__ b2v, int dbl) {
    extern __shared__ char sm[];
    tgemm_body<64, 2>(sm, g_O, &g_WtH[3*65536], &g_WtL[3*65536], bo, nullptr, 0,
                      g1v, b1v, g2v, b2v, dbl);
}

// ---------------- time attention: tensor-core flash from bf16 images ----------------
#define KT 48
__global__ void __launch_bounds__(256) k_attn_time() {
    __shared__ __nv_bfloat16 sQH[128*40], sQL[128*40];
    __shared__ __nv_bfloat16 sKH[48*40],  sKL[48*40];
    __shared__ __nv_bfloat16 sVH[32*56],  sVL[32*56];

    int g  = blockIdx.z;
    int h  = blockIdx.y;
    int qb = blockIdx.x * 128;
    int tid = threadIdx.x;
    int wid = tid >> 5, lane = tid & 31;
    const int base = ((g*8 + h)*336)*32;

    uint32_t uQH = smem_u32(sQH), uQL = smem_u32(sQL);
    uint32_t uKH = smem_u32(sKH), uKL = smem_u32(sKL);
    uint32_t uVH = smem_u32(sVH), uVL = smem_u32(sVL);

    // stage Q (pure copies — already bf16 hi/lo, pre-scaled)
#pragma unroll
    for (int i = 0; i < 2; i++) {
        int idx = tid + 256*i;          // 512
        int r = idx >> 2, q = idx & 3;
        int qi = qb + r; if (qi > 335) qi = 335;
        *(uint4*)&sQH[r*40 + q*8] = *(const uint4*)&g_iQH[base + qi*32 + q*8];
        *(uint4*)&sQL[r*40 + q*8] = *(const uint4*)&g_iQL[base + qi*32 + q*8];
    }
    __syncthreads();

    uint32_t aQoff = (uint32_t)(wid*16 + (lane & 7) + ((lane >> 3) & 1)*8)*80
                   + ((lane >> 4) & 1)*16;
    uint32_t qH[2][4], qL[2][4];
#pragma unroll
    for (int ks = 0; ks < 2; ks++) {
        ldsm4(qH[ks][0], qH[ks][1], qH[ks][2], qH[ks][3], uQH + aQoff + ks*32);
        ldsm4(qL[ks][0], qL[ks][1], qL[ks][2], qL[ks][3], uQL + aQoff + ks*32);
    }

    float o[4][4];
#pragma unroll
    for (int j = 0; j < 4; j++)
#pragma unroll
        for (int q = 0; q < 4; q++) o[j][q] = 0.f;
    float m0 = -1e30f, m1 = -1e30f, sum0 = 0.f, sum1 = 0.f;

    uint32_t kOff = (uint32_t)((lane & 7) + ((lane >> 4) & 1)*8)*80 + ((lane >> 3) & 1)*16;
    uint32_t vOff = (uint32_t)((lane & 7) + ((lane >> 4) & 1)*8)*112 + ((lane >> 3) & 1)*16;

    // stage K/V tile 0 (copies + V transpose)
#pragma unroll
    for (int i = 0; i < 6; i++) {
        int p = tid + 256*i;            // 0..1535
        int img = p >= 768;
        int q = img ? (p - 768) : p;
        int r = q >> 4, c2 = (q & 15)*2;
        const __nv_bfloat16* ks = img ? g_iKL : g_iKH;
        *(uint32_t*)&((img ? sKL : sKH)[r*40 + c2]) =
            *(const uint32_t*)&ks[base + r*32 + c2];
        const __nv_bfloat16* vs = img ? g_iVL : g_iVH;
        uint32_t vv = *(const uint32_t*)&vs[base + r*32 + c2];
        __nv_bfloat162 pv = *(__nv_bfloat162*)&vv;
        __nv_bfloat16* vd = img ? sVL : sVH;
        vd[c2*56 + r]     = pv.x;
        vd[(c2+1)*56 + r] = pv.y;
    }
    __syncthreads();

    uint32_t pK[6], pV[6];
    for (int kt = 0; kt < 7; kt++) {
        if (kt < 6) {
            int kb = (kt + 1)*KT;
#pragma unroll
            for (int i = 0; i < 6; i++) {
                int p = tid + 256*i;
                int img = p >= 768;
                int q = img ? (p - 768) : p;
                int r = q >> 4, c2 = (q & 15)*2;
                pK[i] = *(const uint32_t*)&((img ? g_iKL : g_iKH)[base + (kb + r)*32 + c2]);
                pV[i] = *(const uint32_t*)&((img ? g_iVL : g_iVH)[base + (kb + r)*32 + c2]);
            }
        }

        // scores S (16 x 48) = Q K^T, 3-term bf16 split
        float sc[6][4];
#pragma unroll
        for (int j = 0; j < 6; j++)
#pragma unroll
            for (int q = 0; q < 4; q++) sc[j][q] = 0.f;
#pragma unroll
        for (int ks = 0; ks < 2; ks++) {
#pragma unroll
            for (int ng = 0; ng < 3; ng++) {
                uint32_t bH[4], bL[4];
                ldsm4(bH[0], bH[1], bH[2], bH[3], uKH + kOff + ng*(16*80) + ks*32);
                ldsm4(bL[0], bL[1], bL[2], bL[3], uKL + kOff + ng*(16*80) + ks*32);
                mma16816(sc[2*ng],   qH[ks], &bH[0]);
                mma16816(sc[2*ng+1], qH[ks], &bH[2]);
                mma16816(sc[2*ng],   qH[ks], &bL[0]);
                mma16816(sc[2*ng+1], qH[ks], &bL[2]);
                mma16816(sc[2*ng],   qL[ks], &bH[0]);
                mma16816(sc[2*ng+1], qL[ks], &bH[2]);
            }
        }

        // online softmax
        float t0 = -1e30f, t1 = -1e30f;
#pragma unroll
        for (int j = 0; j < 6; j++) {
            t0 = fmaxf(t0, fmaxf(sc[j][0], sc[j][1]));
            t1 = fmaxf(t1, fmaxf(sc[j][2], sc[j][3]));
        }
        t0 = fmaxf(t0, __shfl_xor_sync(0xffffffffu, t0, 1));
        t0 = fmaxf(t0, __shfl_xor_sync(0xffffffffu, t0, 2));
        t1 = fmaxf(t1, __shfl_xor_sync(0xffffffffu, t1, 1));
        t1 = fmaxf(t1, __shfl_xor_sync(0xffffffffu, t1, 2));
        float nm0 = fmaxf(m0, t0), nm1 = fmaxf(m1, t1);
        float c0 = __expf(m0 - nm0), c1 = __expf(m1 - nm1);
        float ts0 = 0.f, ts1 = 0.f;
#pragma unroll
        for (int j = 0; j < 6; j++) {
            sc[j][0] = __expf(sc[j][0] - nm0);
            sc[j][1] = __expf(sc[j][1] - nm0);
            sc[j][2] = __expf(sc[j][2] - nm1);
            sc[j][3] = __expf(sc[j][3] - nm1);
            ts0 += sc[j][0] + sc[j][1];
            ts1 += sc[j][2] + sc[j][3];
        }
        sum0 = sum0*c0 + ts0;
        sum1 = sum1*c1 + ts1;
#pragma unroll
        for (int j = 0; j < 4; j++) {
            o[j][0] *= c0; o[j][1] *= c0; o[j][2] *= c1; o[j][3] *= c1;
        }
        m0 = nm0; m1 = nm1;

        // PV, 3-term split
#pragma unroll
        for (int kb = 0; kb < 3; kb++) {
            uint32_t aP[4], aR[4];
#pragma unroll
            for (int t = 0; t < 2; t++) {
                int j = 2*kb + t;
                float x0 = sc[j][0], x1 = sc[j][1], x2 = sc[j][2], x3 = sc[j][3];
                __nv_bfloat162 h01 = __floats2bfloat162_rn(x0, x1);
                __nv_bfloat162 h23 = __floats2bfloat162_rn(x2, x3);
                aP[2*t]   = *(uint32_t*)&h01;
                aP[2*t+1] = *(uint32_t*)&h23;
                aR[2*t]   = pk_bf2(x0 - __bfloat162float(h01.x),
                                   x1 - __bfloat162float(h01.y));
                aR[2*t+1] = pk_bf2(x2 - __bfloat162float(h23.x),
                                   x3 - __bfloat162float(h23.y));
            }
#pragma unroll
            for (int ng = 0; ng < 2; ng++) {
                uint32_t vH[4], vL[4];
                ldsm4(vH[0], vH[1], vH[2], vH[3], uVH + vOff + ng*(16*112) + kb*32);
                ldsm4(vL[0], vL[1], vL[2], vL[3], uVL + vOff + ng*(16*112) + kb*32);
                mma16816(o[2*ng],   aP, &vH[0]);
                mma16816(o[2*ng+1], aP, &vH[2]);
                mma16816(o[2*ng],   aP, &vL[0]);
                mma16816(o[2*ng+1], aP, &vL[2]);
                mma16816(o[2*ng],   aR, &vH[0]);
                mma16816(o[2*ng+1], aR, &vH[2]);
            }
        }
        __syncthreads();
        if (kt < 6) {
#pragma unroll
            for (int i = 0; i < 6; i++) {
                int p = tid + 256*i;
                int img = p >= 768;
                int q = img ? (p - 768) : p;
                int r = q >> 4, c2 = (q & 15)*2;
                *(uint32_t*)&((img ? sKL : sKH)[r*40 + c2]) = pK[i];
                __nv_bfloat162 pv = *(__nv_bfloat162*)&pV[i];
                __nv_bfloat16* vd = img ? sVL : sVH;
                vd[c2*56 + r]     = pv.x;
                vd[(c2+1)*56 + r] = pv.y;
            }
            __syncthreads();
        }
    }

    // finalize
    sum0 += __shfl_xor_sync(0xffffffffu, sum0, 1);
    sum0 += __shfl_xor_sync(0xffffffffu, sum0, 2);
    sum1 += __shfl_xor_sync(0xffffffffu, sum1, 1);
    sum1 += __shfl_xor_sync(0xffffffffu, sum1, 2);
    float inv0 = 1.f / sum0, inv1 = 1.f / sum1;
    int q0 = qb + wid*16 + (lane >> 2);
    int q1 = q0 + 8;
    int cbase = h*32 + 2*(lane & 3);
#pragma unroll
    for (int j = 0; j < 4; j++) {
        int col = cbase + 8*j;
        if (q0 < 336) {
            float2 w0; w0.x = o[j][0]*inv0; w0.y = o[j][1]*inv0;
            *(float2*)&g_O[(g*SS + q0)*DD + col] = w0;
        }
        if (q1 < 336) {
            float2 w1; w1.x = o[j][2]*inv1; w1.y = o[j][3]*inv1;
            *(float2*)&g_O[(g*SS + q1)*DD + col] = w1;
        }
    }
}

// ---------------- variable attention (L=8, fp32 path) ----------------
__global__ void __launch_bounds__(64) k_attn_var() {
    __shared__ __align__(16) float Ks[8][256];
    __shared__ __align__(16) float Vs[8][256];

    int bs = blockIdx.x;
    int b = bs / SS;
    int s = bs - b*SS;
    int tid = threadIdx.x;

#pragma unroll
    for (int i = 0; i < 8; i++) {
        int f = tid + 64*i;
        int v = f >> 6;
        int dq = f & 63;
        int ga = ((b*VV + v)*SS + s)*DD + dq*4;
        *(float4*)&Ks[v][dq*4] = *(const float4*)&g_K[ga];
        *(float4*)&Vs[v][dq*4] = *(const float4*)&g_V[ga];
    }
    __syncthreads();

    int qv = tid & 7;
    int h  = tid >> 3;
    const float* qp = &g_Q[((b*VV + qv)*SS + s)*DD + h*32];
    float q[32];
#pragma unroll
    for (int i = 0; i < 8; i++) {
        float4 v4 = *(const float4*)&qp[i*4];
        q[i*4+0] = v4.x; q[i*4+1] = v4.y; q[i*4+2] = v4.z; q[i*4+3] = v4.w;
    }
    float sc[8];
    float mx = -1e30f;
#pragma unroll
    for (int v = 0; v < 8; v++) {
        float t = 0.f;
#pragma unroll
        for (int d = 0; d < 32; d++) t += q[d]*Ks[v][h*32 + d];
        t *= RSQRT_DK;
        sc[v] = t;
        mx = fmaxf(mx, t);
    }
    float sum = 0.f;
#pragma unroll
    for (int v = 0; v < 8; v++) { sc[v] = __expf(sc[v] - mx); sum += sc[v]; }
    float inv = 1.f / sum;

    float o[32];
#pragma unroll
    for (int d = 0; d < 32; d++) o[d] = 0.f;
#pragma unroll
    for (int v = 0; v < 8; v++)
#pragma unroll
        for (int d = 0; d < 32; d++) o[d] += sc[v]*Vs[v][h*32 + d];

    float* op = &g_O[((b*VV + qv)*SS + s)*DD + h*32];
#pragma unroll
    for (int i = 0; i < 8; i++) {
        float4 v4;
        v4.x = o[i*4+0]*inv; v4.y = o[i*4+1]*inv;
        v4.z = o[i*4+2]*inv; v4.w = o[i*4+3]*inv;
        *(float4*)&op[i*4] = v4;
    }
}

// ---------------- final projection ----------------
__global__ void k_out_init(const float* __restrict__ pb, float* __restrict__ out) {
    int i = blockIdx.x*256 + threadIdx.x;
    if (i < BB*PP*VV) {
        int p = (i % (PP*VV)) >> 3;
        out[i] = pb[p];
    }
}

__global__ void __launch_bounds__(256) k_proj(const float* __restrict__ W,
                                              float* __restrict__ out) {
    __shared__ float Ws[64][96];
    __shared__ float Es[16][64];
    int k0 = blockIdx.x * 512;
    int tid = threadIdx.x;

    float acc[6];
    const float* erow[6];
    int wcol[6], oidx[6];
#pragma unroll
    for (int i = 0; i < 6; i++) {
        int qq = tid + 256*i;
        int bv = qq / 96;
        int p  = qq - bv*96;
        acc[i] = 0.f;
        erow[i] = &Es[bv][0];
        wcol[i] = p;
        oidx[i] = (bv >> 3)*(PP*VV) + p*VV + (bv & 7);
    }

    for (int kt = 0; kt < 8; kt++) {
        int kb = k0 + kt*64;
        __syncthreads();
#pragma unroll
        for (int i = 0; i < 6; i++) {
            int f = tid + 256*i;
            int kk = f / 24;
            int pq = f - kk*24;
            *(float4*)&Ws[kk][pq*4] = *(const float4*)&W[(kb + kk)*PP + pq*4];
        }
        {
            int bv = tid >> 4;
            int kq = tid & 15;
            *(float4*)&Es[bv][kq*4] = *(const float4*)&g_E[bv*SD + kb + kq*4];
        }
        __syncthreads();
        for (int kk = 0; kk < 64; kk++) {
#pragma unroll
            for (int i = 0; i < 6; i++)
                acc[i] += erow[i][kk] * Ws[kk][wcol[i]];
        }
    }
#pragma unroll
    for (int i = 0; i < 6; i++)
        atomicAdd(&out[oidx[i]], acc[i]);
}

// ---------------- launch ----------------
extern "C" void kernel_launch(void* const* d_in, const int* in_sizes, int n_in,
                              void* d_out, int out_size) {
    const float* x      = (const float*)d_in[0];
    const float* emb_w  = (const float*)d_in[1];
    const float* emb_b  = (const float*)d_in[2];
    const float* Wq     = (const float*)d_in[3];
    const float* bq     = (const float*)d_in[4];
    const float* Wk     = (const float*)d_in[5];
    const float* bk     = (const float*)d_in[6];
    const float* Wv     = (const float*)d_in[7];
    const float* bv     = (const float*)d_in[8];
    const float* Wo     = (const float*)d_in[9];
    const float* bo     = (const float*)d_in[10];
    const float* ln1_g  = (const float*)d_in[11];
    const float* ln1_b  = (const float*)d_in[12];
    const float* norm_g = (const float*)d_in[13];
    const float* norm_b = (const float*)d_in[14];
    const float* proj_w = (const float*)d_in[15];
    const float* proj_b = (const float*)d_in[16];
    float* out = (float*)d_out;

    cudaFuncSetAttribute(k_tgemm_qkv_img, cudaFuncAttributeMaxDynamicSharedMemorySize, SMEM_T(128));
    cudaFuncSetAttribute(k_tgemm_qkv_f32, cudaFuncAttributeMaxDynamicSharedMemorySize, SMEM_T(128));
    cudaFuncSetAttribute(k_wo,            cudaFuncAttributeMaxDynamicSharedMemorySize, SMEM_WO);

    k_prep<<<dim3(256, 4), 256>>>(Wq, Wk, Wv, Wo);
    k_embed<<<NT, 256>>>(x, emb_w, emb_b);

    for (int it = 0; it < 10; it++) {
        // phase A: attention over time axis (bf16 image path)
        k_tgemm_qkv_img<<<dim3(42, 3), 512, SMEM_T(128)>>>(bq, bk, bv);
        k_attn_time<<<dim3(3, 8, 16), 256>>>();
        k_wo<<<84, 256, SMEM_WO>>>(bo, ln1_g, ln1_b, norm_g, norm_b, 1);
        // phase B: attention over variable axis (fp32 path)
        k_tgemm_qkv_f32<<<dim3(42, 3), 512, SMEM_T(128)>>>(bq, bk, bv);
        k_attn_var<<<BB*SS, 64>>>();
        k_wo<<<84, 256, SMEM_WO>>>(bo, ln1_g, ln1_b, norm_g, norm_b, 0);
    }

    k_out_init<<<6, 256>>>(proj_b, out);
    k_proj<<<SD/512, 256>>>(proj_w, out);
}

// round 14
// speedup vs baseline: 1.1323x; 1.0240x over previous
#include <cuda_runtime.h>
#include <cuda_bf16.h>
#include <math.h>
#include <stdint.h>

// ---------------- problem constants ----------------
#define BB   2
#define SS   336
#define VV   8
#define DD   256
#define HH   8
#define DK   32
#define PP   96
#define NT   (BB*VV*SS)      // 5376 tokens
#define SD   (SS*DD)         // 86016
#define RSQRT_DK 0.17677669529663687f   // 1/sqrt(32)

// ---------------- scratch ----------------
__device__ float g_E[NT*DD];
__device__ float g_Q[NT*DD];
__device__ float g_K[NT*DD];
__device__ float g_V[NT*DD];
__device__ float g_O[NT*DD];
// transposed bf16 weight images W^T[n][k], hi/lo split: [w(4)][256][256]
__device__ __align__(16) __nv_bfloat16 g_WtH[4*65536];
__device__ __align__(16) __nv_bfloat16 g_WtL[4*65536];
// phase-A QKV bf16 images: [(g*8+h)*336 + s]*32 + d  (Q pre-scaled by 1/sqrt(dk))
#define IMG_ELEMS (128*336*32)
__device__ __align__(16) __nv_bfloat16 g_iQH[IMG_ELEMS], g_iQL[IMG_ELEMS];
__device__ __align__(16) __nv_bfloat16 g_iKH[IMG_ELEMS], g_iKL[IMG_ELEMS];
__device__ __align__(16) __nv_bfloat16 g_iVH[IMG_ELEMS], g_iVL[IMG_ELEMS];

// ---------------- helpers ----------------
__device__ __forceinline__ uint32_t smem_u32(const void* p) {
    uint32_t a;
    asm("{ .reg .u64 t; cvta.to.shared.u64 t, %1; cvt.u32.u64 %0, t; }" : "=r"(a) : "l"(p));
    return a;
}
__device__ __forceinline__ void ldsm4(uint32_t& r0, uint32_t& r1, uint32_t& r2, uint32_t& r3,
                                      uint32_t a) {
    asm volatile("ldmatrix.sync.aligned.m8n8.x4.shared.b16 {%0,%1,%2,%3}, [%4];"
        : "=r"(r0), "=r"(r1), "=r"(r2), "=r"(r3) : "r"(a));
}
__device__ __forceinline__ void ldsm4t(uint32_t& r0, uint32_t& r1, uint32_t& r2, uint32_t& r3,
                                       uint32_t a) {
    asm volatile("ldmatrix.sync.aligned.m8n8.x4.trans.shared.b16 {%0,%1,%2,%3}, [%4];"
        : "=r"(r0), "=r"(r1), "=r"(r2), "=r"(r3) : "r"(a));
}
__device__ __forceinline__ void mma16816(float* c, const uint32_t* a, const uint32_t* b) {
    asm volatile("mma.sync.aligned.m16n8k16.row.col.f32.bf16.bf16.f32 "
        "{%0,%1,%2,%3}, {%4,%5,%6,%7}, {%8,%9}, {%0,%1,%2,%3};"
        : "+f"(c[0]), "+f"(c[1]), "+f"(c[2]), "+f"(c[3])
        : "r"(a[0]), "r"(a[1]), "r"(a[2]), "r"(a[3]), "r"(b[0]), "r"(b[1]));
}
__device__ __forceinline__ void cpa16(uint32_t dst, const void* src) {
    asm volatile("cp.async.cg.shared.global [%0], [%1], 16;" :: "r"(dst), "l"(src));
}
#define CPA_COMMIT() asm volatile("cp.async.commit_group;" ::: "memory")
#define CPA_WAIT0()  asm volatile("cp.async.wait_group 0;" ::: "memory")

__device__ __forceinline__ uint32_t pk_bf2(float lo, float hi) {
    __nv_bfloat162 h = __floats2bfloat162_rn(lo, hi);
    return *(uint32_t*)&h;
}

// ---------------- embed ----------------
__global__ void k_embed(const float* __restrict__ x,
                        const float* __restrict__ ew,
                        const float* __restrict__ eb) {
    int idx = blockIdx.x * 256 + threadIdx.x;
    int d = idx & 255;
    int t = idx >> 8;
    int b = t / (VV*SS);
    int r = t - b*(VV*SS);
    int v = r / SS;
    int s = r - v*SS;
    g_E[idx] = x[(b*SS + s)*VV + v] * ew[d] + eb[d];
}

// ---------------- weight prep: W^T + bf16 hi/lo split ----------------
__global__ void k_prep(const float* __restrict__ Wq, const float* __restrict__ Wk,
                       const float* __restrict__ Wv, const float* __restrict__ Wo) {
    int e = blockIdx.x * 256 + threadIdx.x;   // 0..65535
    int w = blockIdx.y;
    int n = e >> 8, k = e & 255;
    const float* W = (w == 0) ? Wq : (w == 1) ? Wk : (w == 2) ? Wv : Wo;
    float a = W[k*256 + n];
    __nv_bfloat16 h = __float2bfloat16(a);
    __nv_bfloat16 l = __float2bfloat16(a - __bfloat162float(h));
    g_WtH[w*65536 + n*256 + k] = h;
    g_WtL[w*65536 + n*256 + k] = l;
}

// ---------------- pipelined mma.sync bf16x3 GEMM (templated tile) ----------------
#define SMEM_T(TM)  ((TM)*576 + 147456)
#define SMEM_WO     (SMEM_T(64) + 2048)

template<int TM, int MODE>
__device__ __forceinline__ void tgemm_body(char* sm, const float* __restrict__ A,
                                           const __nv_bfloat16* __restrict__ WtH,
                                           const __nv_bfloat16* __restrict__ WtL,
                                           const float* __restrict__ bias,
                                           float* __restrict__ C, int y,
                                           const float* g1v, const float* b1v,
                                           const float* g2v, const float* b2v, int dbl) {
    constexpr int NTHR = TM*4;
    constexpr int MW   = TM/32;
    constexpr int A_SPL = TM*144;
    constexpr int A_BUF = 2*A_SPL;
    constexpr int GB0   = 2*A_BUF;
    constexpr int B_ITERS = 2048/NTHR;
    const int tid = threadIdx.x;
    const int wid = tid >> 5, lane = tid & 31;
    const int m0 = blockIdx.x * TM;
    const int wm = (wid % MW) * 32;
    const int wn = (wid / MW) * 64;
    uint32_t sb = smem_u32(sm);

    float acc[2][8][4];
#pragma unroll
    for (int i = 0; i < 2; i++)
#pragma unroll
        for (int j = 0; j < 8; j++)
#pragma unroll
            for (int q = 0; q < 4; q++) acc[i][j][q] = 0.f;

    uint32_t aRow = wm + (lane & 7) + ((lane >> 3) & 1) * 8;
    uint32_t aOff = aRow*144 + ((lane >> 4) & 1)*16;
    uint32_t bRow = wn + (lane & 7) + ((lane >> 4) & 1) * 8;
    uint32_t bOff = bRow*144 + ((lane >> 3) & 1)*16;

    float4 av[4];
    {
        const float4* Ag = (const float4*)(A + m0*256);
#pragma unroll
        for (int i = 0; i < 4; i++) {
            int f = tid + NTHR*i;
            av[i] = Ag[(f >> 4)*64 + (f & 15)];
        }
#pragma unroll
        for (int i = 0; i < B_ITERS; i++) {
            int f = tid + NTHR*i;
            int r = f >> 3, q = f & 7;
            uint32_t off = (uint32_t)r*144 + (uint32_t)q*16;
            cpa16(sb + GB0 + off, WtH + (r << 8) + q*8);
            cpa16(sb + GB0 + 36864 + off, WtL + (r << 8) + q*8);
        }
        CPA_COMMIT();
    }

#pragma unroll
    for (int kc = 0; kc < 4; kc++) {
        int buf = kc & 1;
        uint32_t gaB = buf*A_BUF;
        uint32_t gbB = GB0 + buf*73728;
#pragma unroll
        for (int i = 0; i < 4; i++) {
            int f = tid + NTHR*i;
            int r = f >> 4, q = f & 15;
            float4 v = av[i];
            __nv_bfloat16 h0 = __float2bfloat16(v.x);
            __nv_bfloat16 h1 = __float2bfloat16(v.y);
            __nv_bfloat16 h2 = __float2bfloat16(v.z);
            __nv_bfloat16 h3 = __float2bfloat16(v.w);
            __nv_bfloat16 l0 = __float2bfloat16(v.x - __bfloat162float(h0));
            __nv_bfloat16 l1 = __float2bfloat16(v.y - __bfloat162float(h1));
            __nv_bfloat16 l2 = __float2bfloat16(v.z - __bfloat162float(h2));
            __nv_bfloat16 l3 = __float2bfloat16(v.w - __bfloat162float(h3));
            uint2 hp, lp;
            hp.x = (uint32_t)__bfloat16_as_ushort(h0) | ((uint32_t)__bfloat16_as_ushort(h1) << 16);
            hp.y = (uint32_t)__bfloat16_as_ushort(h2) | ((uint32_t)__bfloat16_as_ushort(h3) << 16);
            lp.x = (uint32_t)__bfloat16_as_ushort(l0) | ((uint32_t)__bfloat16_as_ushort(l1) << 16);
            lp.y = (uint32_t)__bfloat16_as_ushort(l2) | ((uint32_t)__bfloat16_as_ushort(l3) << 16);
            uint32_t off = (uint32_t)r*144 + (uint32_t)q*8;
            *(uint2*)(sm + gaB + off)         = hp;
            *(uint2*)(sm + gaB + A_SPL + off) = lp;
        }
        CPA_WAIT0();
        __syncthreads();

        if (kc < 3) {
            const float4* Ag = (const float4*)(A + m0*256 + (kc + 1)*64);
#pragma unroll
            for (int i = 0; i < 4; i++) {
                int f = tid + NTHR*i;
                av[i] = Ag[(f >> 4)*64 + (f & 15)];
            }
            uint32_t gbN = GB0 + (buf ^ 1)*73728;
#pragma unroll
            for (int i = 0; i < B_ITERS; i++) {
                int f = tid + NTHR*i;
                int r = f >> 3, q = f & 7;
                uint32_t off = (uint32_t)r*144 + (uint32_t)q*16;
                cpa16(sb + gbN + off, WtH + (r << 8) + (kc + 1)*64 + q*8);
                cpa16(sb + gbN + 36864 + off, WtL + (r << 8) + (kc + 1)*64 + q*8);
            }
            CPA_COMMIT();
        }

        uint32_t aB = sb + gaB + aOff;
        uint32_t bB = sb + gbB + bOff;
#pragma unroll
        for (int ks = 0; ks < 4; ks++) {
            uint32_t aH[2][4], aL[2][4], bH[4][4], bL[4][4];
#pragma unroll
            for (int i = 0; i < 2; i++) {
                ldsm4(aH[i][0], aH[i][1], aH[i][2], aH[i][3],
                      aB + (uint32_t)i*2304 + (uint32_t)ks*32);
                ldsm4(aL[i][0], aL[i][1], aL[i][2], aL[i][3],
                      aB + (uint32_t)A_SPL + (uint32_t)i*2304 + (uint32_t)ks*32);
            }
#pragma unroll
            for (int j = 0; j < 4; j++) {
                ldsm4(bH[j][0], bH[j][1], bH[j][2], bH[j][3],
                      bB + (uint32_t)j*2304 + (uint32_t)ks*32);
                ldsm4(bL[j][0], bL[j][1], bL[j][2], bL[j][3],
                      bB + 36864u + (uint32_t)j*2304 + (uint32_t)ks*32);
            }
#pragma unroll
            for (int i = 0; i < 2; i++)
#pragma unroll
                for (int j = 0; j < 4; j++) {
                    mma16816(acc[i][2*j],   aH[i], &bH[j][0]);
                    mma16816(acc[i][2*j+1], aH[i], &bH[j][2]);
                    mma16816(acc[i][2*j],   aH[i], &bL[j][0]);
                    mma16816(acc[i][2*j+1], aH[i], &bL[j][2]);
                    mma16816(acc[i][2*j],   aL[i], &bH[j][0]);
                    mma16816(acc[i][2*j+1], aL[i], &bH[j][2]);
                }
        }
        __syncthreads();
    }

    // ---- epilogue ----
    int tr = lane >> 2, tc = (lane & 3) * 2;
    float2 bb[8];
#pragma unroll
    for (int j = 0; j < 8; j++) {
        int cl = wn + 8*j + tc;
        bb[j].x = __ldg(&bias[cl]);
        bb[j].y = __ldg(&bias[cl+1]);
    }
    if (MODE == 0) {
#pragma unroll
        for (int i = 0; i < 2; i++) {
            int r0 = m0 + wm + 16*i + tr;
#pragma unroll
            for (int j = 0; j < 8; j++) {
                int cl = wn + 8*j + tc;
                float2 o0, o1;
                o0.x = acc[i][j][0] + bb[j].x; o0.y = acc[i][j][1] + bb[j].y;
                o1.x = acc[i][j][2] + bb[j].x; o1.y = acc[i][j][3] + bb[j].y;
                *(float2*)&C[r0*256 + cl]     = o0;
                *(float2*)&C[(r0+8)*256 + cl] = o1;
            }
        }
    } else if (MODE == 1) {
        float scale = (y == 0) ? RSQRT_DK : 1.f;
        __nv_bfloat16 *iH, *iL;
        if (y == 0)      { iH = g_iQH; iL = g_iQL; }
        else if (y == 1) { iH = g_iKH; iL = g_iKL; }
        else             { iH = g_iVH; iL = g_iVL; }
#pragma unroll
        for (int i = 0; i < 2; i++) {
            int r0 = m0 + wm + 16*i + tr;
            int r1 = r0 + 8;
            int ga0 = r0 / 336, s0 = r0 - ga0*336;
            int ga1 = r1 / 336, s1 = r1 - ga1*336;
#pragma unroll
            for (int j = 0; j < 8; j++) {
                int cl = wn + 8*j + tc;
                int hh = cl >> 5, dd = cl & 31;
                float v0 = (acc[i][j][0] + bb[j].x) * scale;
                float v1 = (acc[i][j][1] + bb[j].y) * scale;
                float v2 = (acc[i][j][2] + bb[j].x) * scale;
                float v3 = (acc[i][j][3] + bb[j].y) * scale;
                __nv_bfloat162 h01 = __floats2bfloat162_rn(v0, v1);
                __nv_bfloat162 h23 = __floats2bfloat162_rn(v2, v3);
                int idx0 = (((ga0 << 3) + hh)*336 + s0)*32 + dd;
                int idx1 = (((ga1 << 3) + hh)*336 + s1)*32 + dd;
                *(uint32_t*)&iH[idx0] = *(uint32_t*)&h01;
                *(uint32_t*)&iL[idx0] = pk_bf2(v0 - __bfloat162float(h01.x),
                                               v1 - __bfloat162float(h01.y));
                *(uint32_t*)&iH[idx1] = *(uint32_t*)&h23;
                *(uint32_t*)&iL[idx1] = pk_bf2(v2 - __bfloat162float(h23.x),
                                               v3 - __bfloat162float(h23.y));
            }
        }
    } else {
        // MODE 2: fused residual + LN (and optional second LN), output -> g_E
        float* sRed = (float*)(sm + SMEM_T(64));
        const int ng = wid / MW;
#pragma unroll
        for (int i = 0; i < 2; i++) {
            int rg = m0 + wm + 16*i + tr;
#pragma unroll
            for (int j = 0; j < 8; j++) {
                int cl = wn + 8*j + tc;
                float2 e0 = *(const float2*)&g_E[rg*256 + cl];
                float2 e1 = *(const float2*)&g_E[(rg+8)*256 + cl];
                acc[i][j][0] += bb[j].x + e0.x; acc[i][j][1] += bb[j].y + e0.y;
                acc[i][j][2] += bb[j].x + e1.x; acc[i][j][3] += bb[j].y + e1.y;
            }
        }
        int rounds = 1 + dbl;
        for (int rd = 0; rd < rounds; rd++) {
            const float* gv  = rd ? g2v : g1v;
            const float* bv2 = rd ? b2v : b1v;
#pragma unroll
            for (int i = 0; i < 2; i++) {
                float s0 = 0.f, q0 = 0.f, s1 = 0.f, q1 = 0.f;
#pragma unroll
                for (int j = 0; j < 8; j++) {
                    s0 += acc[i][j][0] + acc[i][j][1];
                    q0 += acc[i][j][0]*acc[i][j][0] + acc[i][j][1]*acc[i][j][1];
                    s1 += acc[i][j][2] + acc[i][j][3];
                    q1 += acc[i][j][2]*acc[i][j][2] + acc[i][j][3]*acc[i][j][3];
                }
#pragma unroll
                for (int o = 1; o <= 2; o <<= 1) {
                    s0 += __shfl_xor_sync(0xffffffffu, s0, o);
                    q0 += __shfl_xor_sync(0xffffffffu, q0, o);
                    s1 += __shfl_xor_sync(0xffffffffu, s1, o);
                    q1 += __shfl_xor_sync(0xffffffffu, q1, o);
                }
                if ((lane & 3) == 0) {
                    int r0l = wm + 16*i + tr;
                    sRed[(r0l*4 + ng)*2]         = s0;
                    sRed[(r0l*4 + ng)*2 + 1]     = q0;
                    sRed[((r0l+8)*4 + ng)*2]     = s1;
                    sRed[((r0l+8)*4 + ng)*2 + 1] = q1;
                }
            }
            __syncthreads();
            float mu[2][2], rr[2][2];
#pragma unroll
            for (int i = 0; i < 2; i++) {
                int r0l = wm + 16*i + tr;
                float S0 = 0.f, Q0 = 0.f, S1 = 0.f, Q1 = 0.f;
#pragma unroll
                for (int n = 0; n < 4; n++) {
                    S0 += sRed[(r0l*4 + n)*2];     Q0 += sRed[(r0l*4 + n)*2 + 1];
                    S1 += sRed[((r0l+8)*4 + n)*2]; Q1 += sRed[((r0l+8)*4 + n)*2 + 1];
                }
                mu[i][0] = S0 * (1.f/256.f);
                rr[i][0] = rsqrtf(Q0*(1.f/256.f) - mu[i][0]*mu[i][0] + 1e-5f);
                mu[i][1] = S1 * (1.f/256.f);
                rr[i][1] = rsqrtf(Q1*(1.f/256.f) - mu[i][1]*mu[i][1] + 1e-5f);
            }
            __syncthreads();
#pragma unroll
            for (int i = 0; i < 2; i++)
#pragma unroll
                for (int j = 0; j < 8; j++) {
                    int cl = wn + 8*j + tc;
                    float gg0 = __ldg(&gv[cl]),  gg1 = __ldg(&gv[cl+1]);
                    float bb0 = __ldg(&bv2[cl]), bb1 = __ldg(&bv2[cl+1]);
                    acc[i][j][0] = (acc[i][j][0] - mu[i][0])*rr[i][0]*gg0 + bb0;
                    acc[i][j][1] = (acc[i][j][1] - mu[i][0])*rr[i][0]*gg1 + bb1;
                    acc[i][j][2] = (acc[i][j][2] - mu[i][1])*rr[i][1]*gg0 + bb0;
                    acc[i][j][3] = (acc[i][j][3] - mu[i][1])*rr[i][1]*gg1 + bb1;
                }
        }
#pragma unroll
        for (int i = 0; i < 2; i++) {
            int rg = m0 + wm + 16*i + tr;
#pragma unroll
            for (int j = 0; j < 8; j++) {
                int cl = wn + 8*j + tc;
                float2 o0, o1;
                o0.x = acc[i][j][0]; o0.y = acc[i][j][1];
                o1.x = acc[i][j][2]; o1.y = acc[i][j][3];
                *(float2*)&g_E[rg*256 + cl]     = o0;
                *(float2*)&g_E[(rg+8)*256 + cl] = o1;
            }
        }
    }
}

__global__ void __launch_bounds__(512, 1)
k_tgemm_qkv_img(const float* __restrict__ bq, const float* __restrict__ bk,
                const float* __restrict__ bv) {
    extern __shared__ char sm[];
    int y = blockIdx.y;
    tgemm_body<128, 1>(sm, g_E, &g_WtH[y*65536], &g_WtL[y*65536],
                       (y == 0) ? bq : (y == 1) ? bk : bv, nullptr, y,
                       nullptr, nullptr, nullptr, nullptr, 0);
}

__global__ void __launch_bounds__(512, 1)
k_tgemm_qkv_f32(const float* __restrict__ bq, const float* __restrict__ bk,
                const float* __restrict__ bv) {
    extern __shared__ char sm[];
    int y = blockIdx.y;
    float* C = (y == 0) ? g_Q : (y == 1) ? g_K : g_V;
    tgemm_body<128, 0>(sm, g_E, &g_WtH[y*65536], &g_WtL[y*65536],
                       (y == 0) ? bq : (y == 1) ? bk : bv, C, y,
                       nullptr, nullptr, nullptr, nullptr, 0);
}

__global__ void __launch_bounds__(256, 1)
k_wo(const float* __restrict__ bo,
     const float* __restrict__ g1v, const float* __restrict__ b1v,
     const float* __restrict__ g2v, const float* __restrict__ b2v, int dbl) {
    extern __shared__ char sm[];
    tgemm_body<64, 2>(sm, g_O, &g_WtH[3*65536], &g_WtL[3*65536], bo, nullptr, 0,
                      g1v, b1v, g2v, b2v, dbl);
}

// ---------------- time attention: cp.async double-buffered flash ----------------
// dynamic smem: QH[0,10240) QL[10240,20480) KV[20480, 20480+30720)
// per KV buffer (15360 B): KH@0 KL@3840 VH@7680 VL@11520; rows [key][d] pitch 80B
#define ATT_SMEM 51200
#define KT 48
__global__ void __launch_bounds__(256) k_attn_time() {
    extern __shared__ char asm_[];
    int g  = blockIdx.z;
    int h  = blockIdx.y;
    int qb = blockIdx.x * 128;
    int tid = threadIdx.x;
    int wid = tid >> 5, lane = tid & 31;
    const int base = ((g*8 + h)*336)*32;

    uint32_t sb  = smem_u32(asm_);
    uint32_t uQH = sb, uQL = sb + 10240, uKV = sb + 20480;

    // stage Q (pure copies — already bf16 hi/lo, pre-scaled)
#pragma unroll
    for (int i = 0; i < 2; i++) {
        int idx = tid + 256*i;          // 512
        int r = idx >> 2, q = idx & 3;
        int qi = qb + r; if (qi > 335) qi = 335;
        *(uint4*)(asm_ + r*80 + q*16)         = *(const uint4*)&g_iQH[base + qi*32 + q*8];
        *(uint4*)(asm_ + 10240 + r*80 + q*16) = *(const uint4*)&g_iQL[base + qi*32 + q*8];
    }

    // stage K/V tile 0 via cp.async (3 x 16B per thread)
#pragma unroll
    for (int i = 0; i < 3; i++) {
        int f = tid + 256*i;            // 0..767
        int isL = f >= 384; int g2 = isL ? f - 384 : f;
        int isV = g2 >= 192; int e = isV ? g2 - 192 : g2;
        int r = e >> 2, q = e & 3;
        const __nv_bfloat16* src = isV ? (isL ? g_iVL : g_iVH)
                                       : (isL ? g_iKL : g_iKH);
        uint32_t dst = uKV + (uint32_t)(isV*7680 + isL*3840) + (uint32_t)r*80 + (uint32_t)q*16;
        cpa16(dst, src + base + r*32 + q*8);
    }
    CPA_COMMIT();
    __syncthreads();   // Q ready (K/V via wait_group below)

    uint32_t aQoff = (uint32_t)(wid*16 + (lane & 7) + ((lane >> 3) & 1)*8)*80
                   + ((lane >> 4) & 1)*16;
    uint32_t qH[2][4], qL[2][4];
#pragma unroll
    for (int ks = 0; ks < 2; ks++) {
        ldsm4(qH[ks][0], qH[ks][1], qH[ks][2], qH[ks][3], uQH + aQoff + ks*32);
        ldsm4(qL[ks][0], qL[ks][1], qL[ks][2], qL[ks][3], uQL + aQoff + ks*32);
    }

    float o[4][4];
#pragma unroll
    for (int j = 0; j < 4; j++)
#pragma unroll
        for (int q = 0; q < 4; q++) o[j][q] = 0.f;
    float m0 = -1e30f, m1 = -1e30f, sum0 = 0.f, sum1 = 0.f;

    // K (B-operand, non-trans): rows = key, halves over d
    uint32_t kOff = (uint32_t)((lane & 7) + ((lane >> 4) & 1)*8)*80 + ((lane >> 3) & 1)*16;
    // V (B-operand via ldsm.trans on [key][d]): rows = key (bit3), d-half via bit4
    uint32_t vOffT = (uint32_t)((lane & 7) + ((lane >> 3) & 1)*8)*80 + ((lane >> 4) & 1)*16;

    for (int kt = 0; kt < 7; kt++) {
        CPA_WAIT0();
        __syncthreads();
        if (kt < 6) {
            int kb0 = (kt + 1)*KT;
            uint32_t bufn = uKV + (uint32_t)(((kt + 1) & 1))*15360;
#pragma unroll
            for (int i = 0; i < 3; i++) {
                int f = tid + 256*i;
                int isL = f >= 384; int g2 = isL ? f - 384 : f;
                int isV = g2 >= 192; int e = isV ? g2 - 192 : g2;
                int r = e >> 2, q = e & 3;
                const __nv_bfloat16* src = isV ? (isL ? g_iVL : g_iVH)
                                               : (isL ? g_iKL : g_iKH);
                uint32_t dst = bufn + (uint32_t)(isV*7680 + isL*3840)
                             + (uint32_t)r*80 + (uint32_t)q*16;
                cpa16(dst, src + base + (kb0 + r)*32 + q*8);
            }
            CPA_COMMIT();
        }
        uint32_t kvb = uKV + (uint32_t)(kt & 1)*15360;
        uint32_t uKHb = kvb, uKLb = kvb + 3840;
        uint32_t uVHb = kvb + 7680, uVLb = kvb + 11520;

        // scores S (16 x 48) = Q K^T, 3-term bf16 split
        float sc[6][4];
#pragma unroll
        for (int j = 0; j < 6; j++)
#pragma unroll
            for (int q = 0; q < 4; q++) sc[j][q] = 0.f;
#pragma unroll
        for (int ks = 0; ks < 2; ks++) {
#pragma unroll
            for (int ng = 0; ng < 3; ng++) {
                uint32_t bH[4], bL[4];
                ldsm4(bH[0], bH[1], bH[2], bH[3], uKHb + kOff + ng*(16*80) + ks*32);
                ldsm4(bL[0], bL[1], bL[2], bL[3], uKLb + kOff + ng*(16*80) + ks*32);
                mma16816(sc[2*ng],   qH[ks], &bH[0]);
                mma16816(sc[2*ng+1], qH[ks], &bH[2]);
                mma16816(sc[2*ng],   qH[ks], &bL[0]);
                mma16816(sc[2*ng+1], qH[ks], &bL[2]);
                mma16816(sc[2*ng],   qL[ks], &bH[0]);
                mma16816(sc[2*ng+1], qL[ks], &bH[2]);
            }
        }

        // online softmax
        float t0 = -1e30f, t1 = -1e30f;
#pragma unroll
        for (int j = 0; j < 6; j++) {
            t0 = fmaxf(t0, fmaxf(sc[j][0], sc[j][1]));
            t1 = fmaxf(t1, fmaxf(sc[j][2], sc[j][3]));
        }
        t0 = fmaxf(t0, __shfl_xor_sync(0xffffffffu, t0, 1));
        t0 = fmaxf(t0, __shfl_xor_sync(0xffffffffu, t0, 2));
        t1 = fmaxf(t1, __shfl_xor_sync(0xffffffffu, t1, 1));
        t1 = fmaxf(t1, __shfl_xor_sync(0xffffffffu, t1, 2));
        float nm0 = fmaxf(m0, t0), nm1 = fmaxf(m1, t1);
        float c0 = __expf(m0 - nm0), c1 = __expf(m1 - nm1);
        float ts0 = 0.f, ts1 = 0.f;
#pragma unroll
        for (int j = 0; j < 6; j++) {
            sc[j][0] = __expf(sc[j][0] - nm0);
            sc[j][1] = __expf(sc[j][1] - nm0);
            sc[j][2] = __expf(sc[j][2] - nm1);
            sc[j][3] = __expf(sc[j][3] - nm1);
            ts0 += sc[j][0] + sc[j][1];
            ts1 += sc[j][2] + sc[j][3];
        }
        sum0 = sum0*c0 + ts0;
        sum1 = sum1*c1 + ts1;
#pragma unroll
        for (int j = 0; j < 4; j++) {
            o[j][0] *= c0; o[j][1] *= c0; o[j][2] *= c1; o[j][3] *= c1;
        }
        m0 = nm0; m1 = nm1;

        // PV, 3-term split (V via ldsm.trans on [key][d])
#pragma unroll
        for (int kb = 0; kb < 3; kb++) {
            uint32_t aP[4], aR[4];
#pragma unroll
            for (int t = 0; t < 2; t++) {
                int j = 2*kb + t;
                float x0 = sc[j][0], x1 = sc[j][1], x2 = sc[j][2], x3 = sc[j][3];
                __nv_bfloat162 h01 = __floats2bfloat162_rn(x0, x1);
                __nv_bfloat162 h23 = __floats2bfloat162_rn(x2, x3);
                aP[2*t]   = *(uint32_t*)&h01;
                aP[2*t+1] = *(uint32_t*)&h23;
                aR[2*t]   = pk_bf2(x0 - __bfloat162float(h01.x),
                                   x1 - __bfloat162float(h01.y));
                aR[2*t+1] = pk_bf2(x2 - __bfloat162float(h23.x),
                                   x3 - __bfloat162float(h23.y));
            }
#pragma unroll
            for (int ng = 0; ng < 2; ng++) {
                uint32_t vH[4], vL[4];
                ldsm4t(vH[0], vH[1], vH[2], vH[3], uVHb + vOffT + kb*1280 + ng*32);
                ldsm4t(vL[0], vL[1], vL[2], vL[3], uVLb + vOffT + kb*1280 + ng*32);
                mma16816(o[2*ng],   aP, &vH[0]);
                mma16816(o[2*ng+1], aP, &vH[2]);
                mma16816(o[2*ng],   aP, &vL[0]);
                mma16816(o[2*ng+1], aP, &vL[2]);
                mma16816(o[2*ng],   aR, &vH[0]);
                mma16816(o[2*ng+1], aR, &vH[2]);
            }
        }
    }

    // finalize
    sum0 += __shfl_xor_sync(0xffffffffu, sum0, 1);
    sum0 += __shfl_xor_sync(0xffffffffu, sum0, 2);
    sum1 += __shfl_xor_sync(0xffffffffu, sum1, 1);
    sum1 += __shfl_xor_sync(0xffffffffu, sum1, 2);
    float inv0 = 1.f / sum0, inv1 = 1.f / sum1;
    int q0 = qb + wid*16 + (lane >> 2);
    int q1 = q0 + 8;
    int cbase = h*32 + 2*(lane & 3);
#pragma unroll
    for (int j = 0; j < 4; j++) {
        int col = cbase + 8*j;
        if (q0 < 336) {
            float2 w0; w0.x = o[j][0]*inv0; w0.y = o[j][1]*inv0;
            *(float2*)&g_O[(g*SS + q0)*DD + col] = w0;
        }
        if (q1 < 336) {
            float2 w1; w1.x = o[j][2]*inv1; w1.y = o[j][3]*inv1;
            *(float2*)&g_O[(g*SS + q1)*DD + col] = w1;
        }
    }
}

// ---------------- variable attention (L=8, fp32 path) ----------------
__global__ void __launch_bounds__(64) k_attn_var() {
    __shared__ __align__(16) float Ks[8][256];
    __shared__ __align__(16) float Vs[8][256];

    int bs = blockIdx.x;
    int b = bs / SS;
    int s = bs - b*SS;
    int tid = threadIdx.x;

#pragma unroll
    for (int i = 0; i < 8; i++) {
        int f = tid + 64*i;
        int v = f >> 6;
        int dq = f & 63;
        int ga = ((b*VV + v)*SS + s)*DD + dq*4;
        *(float4*)&Ks[v][dq*4] = *(const float4*)&g_K[ga];
        *(float4*)&Vs[v][dq*4] = *(const float4*)&g_V[ga];
    }
    __syncthreads();

    int qv = tid & 7;
    int h  = tid >> 3;
    const float* qp = &g_Q[((b*VV + qv)*SS + s)*DD + h*32];
    float q[32];
#pragma unroll
    for (int i = 0; i < 8; i++) {
        float4 v4 = *(const float4*)&qp[i*4];
        q[i*4+0] = v4.x; q[i*4+1] = v4.y; q[i*4+2] = v4.z; q[i*4+3] = v4.w;
    }
    float sc[8];
    float mx = -1e30f;
#pragma unroll
    for (int v = 0; v < 8; v++) {
        float t = 0.f;
#pragma unroll
        for (int d = 0; d < 32; d++) t += q[d]*Ks[v][h*32 + d];
        t *= RSQRT_DK;
        sc[v] = t;
        mx = fmaxf(mx, t);
    }
    float sum = 0.f;
#pragma unroll
    for (int v = 0; v < 8; v++) { sc[v] = __expf(sc[v] - mx); sum += sc[v]; }
    float inv = 1.f / sum;

    float o[32];
#pragma unroll
    for (int d = 0; d < 32; d++) o[d] = 0.f;
#pragma unroll
    for (int v = 0; v < 8; v++)
#pragma unroll
        for (int d = 0; d < 32; d++) o[d] += sc[v]*Vs[v][h*32 + d];

    float* op = &g_O[((b*VV + qv)*SS + s)*DD + h*32];
#pragma unroll
    for (int i = 0; i < 8; i++) {
        float4 v4;
        v4.x = o[i*4+0]*inv; v4.y = o[i*4+1]*inv;
        v4.z = o[i*4+2]*inv; v4.w = o[i*4+3]*inv;
        *(float4*)&op[i*4] = v4;
    }
}

// ---------------- final projection ----------------
__global__ void k_out_init(const float* __restrict__ pb, float* __restrict__ out) {
    int i = blockIdx.x*256 + threadIdx.x;
    if (i < BB*PP*VV) {
        int p = (i % (PP*VV)) >> 3;
        out[i] = pb[p];
    }
}

__global__ void __launch_bounds__(256) k_proj(const float* __restrict__ W,
                                              float* __restrict__ out) {
    __shared__ float Ws[64][96];
    __shared__ float Es[16][64];
    int k0 = blockIdx.x * 512;
    int tid = threadIdx.x;

    float acc[6];
    const float* erow[6];
    int wcol[6], oidx[6];
#pragma unroll
    for (int i = 0; i < 6; i++) {
        int qq = tid + 256*i;
        int bv = qq / 96;
        int p  = qq - bv*96;
        acc[i] = 0.f;
        erow[i] = &Es[bv][0];
        wcol[i] = p;
        oidx[i] = (bv >> 3)*(PP*VV) + p*VV + (bv & 7);
    }

    for (int kt = 0; kt < 8; kt++) {
        int kb = k0 + kt*64;
        __syncthreads();
#pragma unroll
        for (int i = 0; i < 6; i++) {
            int f = tid + 256*i;
            int kk = f / 24;
            int pq = f - kk*24;
            *(float4*)&Ws[kk][pq*4] = *(const float4*)&W[(kb + kk)*PP + pq*4];
        }
        {
            int bv = tid >> 4;
            int kq = tid & 15;
            *(float4*)&Es[bv][kq*4] = *(const float4*)&g_E[bv*SD + kb + kq*4];
        }
        __syncthreads();
        for (int kk = 0; kk < 64; kk++) {
#pragma unroll
            for (int i = 0; i < 6; i++)
                acc[i] += erow[i][kk] * Ws[kk][wcol[i]];
        }
    }
#pragma unroll
    for (int i = 0; i < 6; i++)
        atomicAdd(&out[oidx[i]], acc[i]);
}

// ---------------- launch ----------------
extern "C" void kernel_launch(void* const* d_in, const int* in_sizes, int n_in,
                              void* d_out, int out_size) {
    const float* x      = (const float*)d_in[0];
    const float* emb_w  = (const float*)d_in[1];
    const float* emb_b  = (const float*)d_in[2];
    const float* Wq     = (const float*)d_in[3];
    const float* bq     = (const float*)d_in[4];
    const float* Wk     = (const float*)d_in[5];
    const float* bk     = (const float*)d_in[6];
    const float* Wv     = (const float*)d_in[7];
    const float* bv     = (const float*)d_in[8];
    const float* Wo     = (const float*)d_in[9];
    const float* bo     = (const float*)d_in[10];
    const float* ln1_g  = (const float*)d_in[11];
    const float* ln1_b  = (const float*)d_in[12];
    const float* norm_g = (const float*)d_in[13];
    const float* norm_b = (const float*)d_in[14];
    const float* proj_w = (const float*)d_in[15];
    const float* proj_b = (const float*)d_in[16];
    float* out = (float*)d_out;

    cudaFuncSetAttribute(k_tgemm_qkv_img, cudaFuncAttributeMaxDynamicSharedMemorySize, SMEM_T(128));
    cudaFuncSetAttribute(k_tgemm_qkv_f32, cudaFuncAttributeMaxDynamicSharedMemorySize, SMEM_T(128));
    cudaFuncSetAttribute(k_wo,            cudaFuncAttributeMaxDynamicSharedMemorySize, SMEM_WO);
    cudaFuncSetAttribute(k_attn_time,     cudaFuncAttributeMaxDynamicSharedMemorySize, ATT_SMEM);

    k_prep<<<dim3(256, 4), 256>>>(Wq, Wk, Wv, Wo);
    k_embed<<<NT, 256>>>(x, emb_w, emb_b);

    for (int it = 0; it < 10; it++) {
        // phase A: attention over time axis (bf16 image path)
        k_tgemm_qkv_img<<<dim3(42, 3), 512, SMEM_T(128)>>>(bq, bk, bv);
        k_attn_time<<<dim3(3, 8, 16), 256, ATT_SMEM>>>();
        k_wo<<<84, 256, SMEM_WO>>>(bo, ln1_g, ln1_b, norm_g, norm_b, 1);
        // phase B: attention over variable axis (fp32 path)
        k_tgemm_qkv_f32<<<dim3(42, 3), 512, SMEM_T(128)>>>(bq, bk, bv);
        k_attn_var<<<BB*SS, 64>>>();
        k_wo<<<84, 256, SMEM_WO>>>(bo, ln1_g, ln1_b, norm_g, norm_b, 0);
    }

    k_out_init<<<6, 256>>>(proj_b, out);
    k_proj<<<SD/512, 256>>>(proj_w, out);
}

// round 15
// speedup vs baseline: 1.1423x; 1.0088x over previous
#include <cuda_runtime.h>
#include <cuda_bf16.h>
#include <math.h>
#include <stdint.h>

// ---------------- problem constants ----------------
#define BB   2
#define SS   336
#define VV   8
#define DD   256
#define HH   8
#define DK   32
#define PP   96
#define NT   (BB*VV*SS)      // 5376 tokens
#define SD   (SS*DD)         // 86016
#define RSQRT_DK 0.17677669529663687f   // 1/sqrt(32)

// ---------------- scratch ----------------
__device__ float g_E[NT*DD];
__device__ float g_Q[NT*DD];
__device__ float g_K[NT*DD];
__device__ float g_V[NT*DD];
__device__ float g_O[NT*DD];
// transposed bf16 weight images W^T[n][k], hi/lo split: [w(4)][256][256]
__device__ __align__(16) __nv_bfloat16 g_WtH[4*65536];
__device__ __align__(16) __nv_bfloat16 g_WtL[4*65536];
// phase-A QKV bf16 images: [(g*8+h)*336 + s]*32 + d  (Q pre-scaled by 1/sqrt(dk))
#define IMG_ELEMS (128*336*32)
__device__ __align__(16) __nv_bfloat16 g_iQH[IMG_ELEMS], g_iQL[IMG_ELEMS];
__device__ __align__(16) __nv_bfloat16 g_iKH[IMG_ELEMS], g_iKL[IMG_ELEMS];
__device__ __align__(16) __nv_bfloat16 g_iVH[IMG_ELEMS], g_iVL[IMG_ELEMS];

// ---------------- helpers ----------------
__device__ __forceinline__ uint32_t smem_u32(const void* p) {
    uint32_t a;
    asm("{ .reg .u64 t; cvta.to.shared.u64 t, %1; cvt.u32.u64 %0, t; }" : "=r"(a) : "l"(p));
    return a;
}
__device__ __forceinline__ void ldsm4(uint32_t& r0, uint32_t& r1, uint32_t& r2, uint32_t& r3,
                                      uint32_t a) {
    asm volatile("ldmatrix.sync.aligned.m8n8.x4.shared.b16 {%0,%1,%2,%3}, [%4];"
        : "=r"(r0), "=r"(r1), "=r"(r2), "=r"(r3) : "r"(a));
}
__device__ __forceinline__ void ldsm4t(uint32_t& r0, uint32_t& r1, uint32_t& r2, uint32_t& r3,
                                       uint32_t a) {
    asm volatile("ldmatrix.sync.aligned.m8n8.x4.trans.shared.b16 {%0,%1,%2,%3}, [%4];"
        : "=r"(r0), "=r"(r1), "=r"(r2), "=r"(r3) : "r"(a));
}
__device__ __forceinline__ void mma16816(float* c, const uint32_t* a, const uint32_t* b) {
    asm volatile("mma.sync.aligned.m16n8k16.row.col.f32.bf16.bf16.f32 "
        "{%0,%1,%2,%3}, {%4,%5,%6,%7}, {%8,%9}, {%0,%1,%2,%3};"
        : "+f"(c[0]), "+f"(c[1]), "+f"(c[2]), "+f"(c[3])
        : "r"(a[0]), "r"(a[1]), "r"(a[2]), "r"(a[3]), "r"(b[0]), "r"(b[1]));
}
__device__ __forceinline__ void cpa16(uint32_t dst, const void* src) {
    asm volatile("cp.async.cg.shared.global [%0], [%1], 16;" :: "r"(dst), "l"(src));
}
#define CPA_COMMIT() asm volatile("cp.async.commit_group;" ::: "memory")
#define CPA_WAIT0()  asm volatile("cp.async.wait_group 0;" ::: "memory")

__device__ __forceinline__ uint32_t pk_bf2(float lo, float hi) {
    __nv_bfloat162 h = __floats2bfloat162_rn(lo, hi);
    return *(uint32_t*)&h;
}

// ---------------- embed ----------------
__global__ void k_embed(const float* __restrict__ x,
                        const float* __restrict__ ew,
                        const float* __restrict__ eb) {
    int idx = blockIdx.x * 256 + threadIdx.x;
    int d = idx & 255;
    int t = idx >> 8;
    int b = t / (VV*SS);
    int r = t - b*(VV*SS);
    int v = r / SS;
    int s = r - v*SS;
    g_E[idx] = x[(b*SS + s)*VV + v] * ew[d] + eb[d];
}

// ---------------- weight prep: W^T + bf16 hi/lo split ----------------
__global__ void k_prep(const float* __restrict__ Wq, const float* __restrict__ Wk,
                       const float* __restrict__ Wv, const float* __restrict__ Wo) {
    int e = blockIdx.x * 256 + threadIdx.x;   // 0..65535
    int w = blockIdx.y;
    int n = e >> 8, k = e & 255;
    const float* W = (w == 0) ? Wq : (w == 1) ? Wk : (w == 2) ? Wv : Wo;
    float a = W[k*256 + n];
    __nv_bfloat16 h = __float2bfloat16(a);
    __nv_bfloat16 l = __float2bfloat16(a - __bfloat162float(h));
    g_WtH[w*65536 + n*256 + k] = h;
    g_WtL[w*65536 + n*256 + k] = l;
}

// ---------------- pipelined mma.sync bf16x3 GEMM (templated tile) ----------------
// Single sync per k-chunk: A-conversion for the NEXT chunk overlaps the current
// chunk's MMAs (writes to the idle A buffer; next top-sync publishes them).
#define SMEM_T(TM)  ((TM)*576 + 147456)
#define SMEM_WO     (SMEM_T(64) + 2048)

template<int TM, int MODE>
__device__ __forceinline__ void tgemm_body(char* sm, const float* __restrict__ A,
                                           const __nv_bfloat16* __restrict__ WtH,
                                           const __nv_bfloat16* __restrict__ WtL,
                                           const float* __restrict__ bias,
                                           float* __restrict__ C, int y,
                                           const float* g1v, const float* b1v,
                                           const float* g2v, const float* b2v, int dbl) {
    constexpr int NTHR = TM*4;
    constexpr int MW   = TM/32;
    constexpr int A_SPL = TM*144;
    constexpr int A_BUF = 2*A_SPL;
    constexpr int GB0   = 2*A_BUF;
    constexpr int B_ITERS = 2048/NTHR;
    const int tid = threadIdx.x;
    const int wid = tid >> 5, lane = tid & 31;
    const int m0 = blockIdx.x * TM;
    const int wm = (wid % MW) * 32;
    const int wn = (wid / MW) * 64;
    uint32_t sb = smem_u32(sm);

    float acc[2][8][4];
#pragma unroll
    for (int i = 0; i < 2; i++)
#pragma unroll
        for (int j = 0; j < 8; j++)
#pragma unroll
            for (int q = 0; q < 4; q++) acc[i][j][q] = 0.f;

    uint32_t aRow = wm + (lane & 7) + ((lane >> 3) & 1) * 8;
    uint32_t aOff = aRow*144 + ((lane >> 4) & 1)*16;
    uint32_t bRow = wn + (lane & 7) + ((lane >> 4) & 1) * 8;
    uint32_t bOff = bRow*144 + ((lane >> 3) & 1)*16;

    // conversion helper: av regs -> A buffer `buf`
    float4 av[4];
    auto convertA = [&](int buf) {
        uint32_t gaB = (uint32_t)buf*A_BUF;
#pragma unroll
        for (int i = 0; i < 4; i++) {
            int f = tid + NTHR*i;
            int r = f >> 4, q = f & 15;
            float4 v = av[i];
            __nv_bfloat16 h0 = __float2bfloat16(v.x);
            __nv_bfloat16 h1 = __float2bfloat16(v.y);
            __nv_bfloat16 h2 = __float2bfloat16(v.z);
            __nv_bfloat16 h3 = __float2bfloat16(v.w);
            __nv_bfloat16 l0 = __float2bfloat16(v.x - __bfloat162float(h0));
            __nv_bfloat16 l1 = __float2bfloat16(v.y - __bfloat162float(h1));
            __nv_bfloat16 l2 = __float2bfloat16(v.z - __bfloat162float(h2));
            __nv_bfloat16 l3 = __float2bfloat16(v.w - __bfloat162float(h3));
            uint2 hp, lp;
            hp.x = (uint32_t)__bfloat16_as_ushort(h0) | ((uint32_t)__bfloat16_as_ushort(h1) << 16);
            hp.y = (uint32_t)__bfloat16_as_ushort(h2) | ((uint32_t)__bfloat16_as_ushort(h3) << 16);
            lp.x = (uint32_t)__bfloat16_as_ushort(l0) | ((uint32_t)__bfloat16_as_ushort(l1) << 16);
            lp.y = (uint32_t)__bfloat16_as_ushort(l2) | ((uint32_t)__bfloat16_as_ushort(l3) << 16);
            uint32_t off = (uint32_t)r*144 + (uint32_t)q*8;
            *(uint2*)(sm + gaB + off)         = hp;
            *(uint2*)(sm + gaB + A_SPL + off) = lp;
        }
    };

    // prologue: A chunk0 -> regs -> bufA0; B chunk0 -> cp.async buf0
    {
        const float4* Ag = (const float4*)(A + m0*256);
#pragma unroll
        for (int i = 0; i < 4; i++) {
            int f = tid + NTHR*i;
            av[i] = Ag[(f >> 4)*64 + (f & 15)];
        }
#pragma unroll
        for (int i = 0; i < B_ITERS; i++) {
            int f = tid + NTHR*i;
            int r = f >> 3, q = f & 7;
            uint32_t off = (uint32_t)r*144 + (uint32_t)q*16;
            cpa16(sb + GB0 + off, WtH + (r << 8) + q*8);
            cpa16(sb + GB0 + 36864 + off, WtL + (r << 8) + q*8);
        }
        CPA_COMMIT();
        convertA(0);
    }

#pragma unroll
    for (int kc = 0; kc < 4; kc++) {
        int buf = kc & 1;
        // prefetch next A chunk into regs (overlaps the wait below)
        if (kc < 3) {
            const float4* Ag = (const float4*)(A + m0*256 + (kc + 1)*64);
#pragma unroll
            for (int i = 0; i < 4; i++) {
                int f = tid + NTHR*i;
                av[i] = Ag[(f >> 4)*64 + (f & 15)];
            }
        }
        CPA_WAIT0();
        __syncthreads();

        // issue next B cp.async (overlaps this chunk's MMAs)
        if (kc < 3) {
            uint32_t gbN = GB0 + (buf ^ 1)*73728;
#pragma unroll
            for (int i = 0; i < B_ITERS; i++) {
                int f = tid + NTHR*i;
                int r = f >> 3, q = f & 7;
                uint32_t off = (uint32_t)r*144 + (uint32_t)q*16;
                cpa16(sb + gbN + off, WtH + (r << 8) + (kc + 1)*64 + q*8);
                cpa16(sb + gbN + 36864 + off, WtL + (r << 8) + (kc + 1)*64 + q*8);
            }
            CPA_COMMIT();
        }

        uint32_t aB = sb + (uint32_t)buf*A_BUF + aOff;
        uint32_t bB = sb + GB0 + (uint32_t)buf*73728 + bOff;
#pragma unroll
        for (int ks = 0; ks < 4; ks++) {
            uint32_t aH[2][4], aL[2][4], bH[4][4], bL[4][4];
#pragma unroll
            for (int i = 0; i < 2; i++) {
                ldsm4(aH[i][0], aH[i][1], aH[i][2], aH[i][3],
                      aB + (uint32_t)i*2304 + (uint32_t)ks*32);
                ldsm4(aL[i][0], aL[i][1], aL[i][2], aL[i][3],
                      aB + (uint32_t)A_SPL + (uint32_t)i*2304 + (uint32_t)ks*32);
            }
#pragma unroll
            for (int j = 0; j < 4; j++) {
                ldsm4(bH[j][0], bH[j][1], bH[j][2], bH[j][3],
                      bB + (uint32_t)j*2304 + (uint32_t)ks*32);
                ldsm4(bL[j][0], bL[j][1], bL[j][2], bL[j][3],
                      bB + 36864u + (uint32_t)j*2304 + (uint32_t)ks*32);
            }
#pragma unroll
            for (int i = 0; i < 2; i++)
#pragma unroll
                for (int j = 0; j < 4; j++) {
                    mma16816(acc[i][2*j],   aH[i], &bH[j][0]);
                    mma16816(acc[i][2*j+1], aH[i], &bH[j][2]);
                    mma16816(acc[i][2*j],   aH[i], &bL[j][0]);
                    mma16816(acc[i][2*j+1], aH[i], &bL[j][2]);
                    mma16816(acc[i][2*j],   aL[i], &bH[j][0]);
                    mma16816(acc[i][2*j+1], aL[i], &bH[j][2]);
                }
        }
        // convert next A chunk into the idle buffer (overlaps MMA tail;
        // published by next iteration's __syncthreads)
        if (kc < 3) convertA(buf ^ 1);
    }
    __syncthreads();

    // ---- epilogue ----
    int tr = lane >> 2, tc = (lane & 3) * 2;
    float2 bb[8];
#pragma unroll
    for (int j = 0; j < 8; j++) {
        int cl = wn + 8*j + tc;
        bb[j].x = __ldg(&bias[cl]);
        bb[j].y = __ldg(&bias[cl+1]);
    }
    if (MODE == 0) {
#pragma unroll
        for (int i = 0; i < 2; i++) {
            int r0 = m0 + wm + 16*i + tr;
#pragma unroll
            for (int j = 0; j < 8; j++) {
                int cl = wn + 8*j + tc;
                float2 o0, o1;
                o0.x = acc[i][j][0] + bb[j].x; o0.y = acc[i][j][1] + bb[j].y;
                o1.x = acc[i][j][2] + bb[j].x; o1.y = acc[i][j][3] + bb[j].y;
                *(float2*)&C[r0*256 + cl]     = o0;
                *(float2*)&C[(r0+8)*256 + cl] = o1;
            }
        }
    } else if (MODE == 1) {
        float scale = (y == 0) ? RSQRT_DK : 1.f;
        __nv_bfloat16 *iH, *iL;
        if (y == 0)      { iH = g_iQH; iL = g_iQL; }
        else if (y == 1) { iH = g_iKH; iL = g_iKL; }
        else             { iH = g_iVH; iL = g_iVL; }
#pragma unroll
        for (int i = 0; i < 2; i++) {
            int r0 = m0 + wm + 16*i + tr;
            int r1 = r0 + 8;
            int ga0 = r0 / 336, s0 = r0 - ga0*336;
            int ga1 = r1 / 336, s1 = r1 - ga1*336;
#pragma unroll
            for (int j = 0; j < 8; j++) {
                int cl = wn + 8*j + tc;
                int hh = cl >> 5, dd = cl & 31;
                float v0 = (acc[i][j][0] + bb[j].x) * scale;
                float v1 = (acc[i][j][1] + bb[j].y) * scale;
                float v2 = (acc[i][j][2] + bb[j].x) * scale;
                float v3 = (acc[i][j][3] + bb[j].y) * scale;
                __nv_bfloat162 h01 = __floats2bfloat162_rn(v0, v1);
                __nv_bfloat162 h23 = __floats2bfloat162_rn(v2, v3);
                int idx0 = (((ga0 << 3) + hh)*336 + s0)*32 + dd;
                int idx1 = (((ga1 << 3) + hh)*336 + s1)*32 + dd;
                *(uint32_t*)&iH[idx0] = *(uint32_t*)&h01;
                *(uint32_t*)&iL[idx0] = pk_bf2(v0 - __bfloat162float(h01.x),
                                               v1 - __bfloat162float(h01.y));
                *(uint32_t*)&iH[idx1] = *(uint32_t*)&h23;
                *(uint32_t*)&iL[idx1] = pk_bf2(v2 - __bfloat162float(h23.x),
                                               v3 - __bfloat162float(h23.y));
            }
        }
    } else {
        // MODE 2: fused residual + LN (and optional second LN), output -> g_E
        float* sRed = (float*)(sm + SMEM_T(64));
        const int ng = wid / MW;
#pragma unroll
        for (int i = 0; i < 2; i++) {
            int rg = m0 + wm + 16*i + tr;
#pragma unroll
            for (int j = 0; j < 8; j++) {
                int cl = wn + 8*j + tc;
                float2 e0 = *(const float2*)&g_E[rg*256 + cl];
                float2 e1 = *(const float2*)&g_E[(rg+8)*256 + cl];
                acc[i][j][0] += bb[j].x + e0.x; acc[i][j][1] += bb[j].y + e0.y;
                acc[i][j][2] += bb[j].x + e1.x; acc[i][j][3] += bb[j].y + e1.y;
            }
        }
        int rounds = 1 + dbl;
        for (int rd = 0; rd < rounds; rd++) {
            const float* gv  = rd ? g2v : g1v;
            const float* bv2 = rd ? b2v : b1v;
#pragma unroll
            for (int i = 0; i < 2; i++) {
                float s0 = 0.f, q0 = 0.f, s1 = 0.f, q1 = 0.f;
#pragma unroll
                for (int j = 0; j < 8; j++) {
                    s0 += acc[i][j][0] + acc[i][j][1];
                    q0 += acc[i][j][0]*acc[i][j][0] + acc[i][j][1]*acc[i][j][1];
                    s1 += acc[i][j][2] + acc[i][j][3];
                    q1 += acc[i][j][2]*acc[i][j][2] + acc[i][j][3]*acc[i][j][3];
                }
#pragma unroll
                for (int o = 1; o <= 2; o <<= 1) {
                    s0 += __shfl_xor_sync(0xffffffffu, s0, o);
                    q0 += __shfl_xor_sync(0xffffffffu, q0, o);
                    s1 += __shfl_xor_sync(0xffffffffu, s1, o);
                    q1 += __shfl_xor_sync(0xffffffffu, q1, o);
                }
                if ((lane & 3) == 0) {
                    int r0l = wm + 16*i + tr;
                    sRed[(r0l*4 + ng)*2]         = s0;
                    sRed[(r0l*4 + ng)*2 + 1]     = q0;
                    sRed[((r0l+8)*4 + ng)*2]     = s1;
                    sRed[((r0l+8)*4 + ng)*2 + 1] = q1;
                }
            }
            __syncthreads();
            float mu[2][2], rr[2][2];
#pragma unroll
            for (int i = 0; i < 2; i++) {
                int r0l = wm + 16*i + tr;
                float S0 = 0.f, Q0 = 0.f, S1 = 0.f, Q1 = 0.f;
#pragma unroll
                for (int n = 0; n < 4; n++) {
                    S0 += sRed[(r0l*4 + n)*2];     Q0 += sRed[(r0l*4 + n)*2 + 1];
                    S1 += sRed[((r0l+8)*4 + n)*2]; Q1 += sRed[((r0l+8)*4 + n)*2 + 1];
                }
                mu[i][0] = S0 * (1.f/256.f);
                rr[i][0] = rsqrtf(Q0*(1.f/256.f) - mu[i][0]*mu[i][0] + 1e-5f);
                mu[i][1] = S1 * (1.f/256.f);
                rr[i][1] = rsqrtf(Q1*(1.f/256.f) - mu[i][1]*mu[i][1] + 1e-5f);
            }
            __syncthreads();
#pragma unroll
            for (int i = 0; i < 2; i++)
#pragma unroll
                for (int j = 0; j < 8; j++) {
                    int cl = wn + 8*j + tc;
                    float gg0 = __ldg(&gv[cl]),  gg1 = __ldg(&gv[cl+1]);
                    float bb0 = __ldg(&bv2[cl]), bb1 = __ldg(&bv2[cl+1]);
                    acc[i][j][0] = (acc[i][j][0] - mu[i][0])*rr[i][0]*gg0 + bb0;
                    acc[i][j][1] = (acc[i][j][1] - mu[i][0])*rr[i][0]*gg1 + bb1;
                    acc[i][j][2] = (acc[i][j][2] - mu[i][1])*rr[i][1]*gg0 + bb0;
                    acc[i][j][3] = (acc[i][j][3] - mu[i][1])*rr[i][1]*gg1 + bb1;
                }
        }
#pragma unroll
        for (int i = 0; i < 2; i++) {
            int rg = m0 + wm + 16*i + tr;
#pragma unroll
            for (int j = 0; j < 8; j++) {
                int cl = wn + 8*j + tc;
                float2 o0, o1;
                o0.x = acc[i][j][0]; o0.y = acc[i][j][1];
                o1.x = acc[i][j][2]; o1.y = acc[i][j][3];
                *(float2*)&g_E[rg*256 + cl]     = o0;
                *(float2*)&g_E[(rg+8)*256 + cl] = o1;
            }
        }
    }
}

__global__ void __launch_bounds__(512, 1)
k_tgemm_qkv_img(const float* __restrict__ bq, const float* __restrict__ bk,
                const float* __restrict__ bv) {
    extern __shared__ char sm[];
    int y = blockIdx.y;
    tgemm_body<128, 1>(sm, g_E, &g_WtH[y*65536], &g_WtL[y*65536],
                       (y == 0) ? bq : (y == 1) ? bk : bv, nullptr, y,
                       nullptr, nullptr, nullptr, nullptr, 0);
}

__global__ void __launch_bounds__(512, 1)
k_tgemm_qkv_f32(const float* __restrict__ bq, const float* __restrict__ bk,
                const float* __restrict__ bv) {
    extern __shared__ char sm[];
    int y = blockIdx.y;
    float* C = (y == 0) ? g_Q : (y == 1) ? g_K : g_V;
    tgemm_body<128, 0>(sm, g_E, &g_WtH[y*65536], &g_WtL[y*65536],
                       (y == 0) ? bq : (y == 1) ? bk : bv, C, y,
                       nullptr, nullptr, nullptr, nullptr, 0);
}

__global__ void __launch_bounds__(256, 1)
k_wo(const float* __restrict__ bo,
     const float* __restrict__ g1v, const float* __restrict__ b1v,
     const float* __restrict__ g2v, const float* __restrict__ b2v, int dbl) {
    extern __shared__ char sm[];
    tgemm_body<64, 2>(sm, g_O, &g_WtH[3*65536], &g_WtL[3*65536], bo, nullptr, 0,
                      g1v, b1v, g2v, b2v, dbl);
}

// ---------------- time attention: cp.async double-buffered flash ----------------
#define ATT_SMEM 51200
#define KT 48
__global__ void __launch_bounds__(256) k_attn_time() {
    extern __shared__ char asm_[];
    int g  = blockIdx.z;
    int h  = blockIdx.y;
    int qb = blockIdx.x * 128;
    int tid = threadIdx.x;
    int wid = tid >> 5, lane = tid & 31;
    const int base = ((g*8 + h)*336)*32;

    uint32_t sb  = smem_u32(asm_);
    uint32_t uQH = sb, uQL = sb + 10240, uKV = sb + 20480;

    // stage Q (pure copies — already bf16 hi/lo, pre-scaled)
#pragma unroll
    for (int i = 0; i < 2; i++) {
        int idx = tid + 256*i;          // 512
        int r = idx >> 2, q = idx & 3;
        int qi = qb + r; if (qi > 335) qi = 335;
        *(uint4*)(asm_ + r*80 + q*16)         = *(const uint4*)&g_iQH[base + qi*32 + q*8];
        *(uint4*)(asm_ + 10240 + r*80 + q*16) = *(const uint4*)&g_iQL[base + qi*32 + q*8];
    }

    // stage K/V tile 0 via cp.async (3 x 16B per thread)
#pragma unroll
    for (int i = 0; i < 3; i++) {
        int f = tid + 256*i;            // 0..767
        int isL = f >= 384; int g2 = isL ? f - 384 : f;
        int isV = g2 >= 192; int e = isV ? g2 - 192 : g2;
        int r = e >> 2, q = e & 3;
        const __nv_bfloat16* src = isV ? (isL ? g_iVL : g_iVH)
                                       : (isL ? g_iKL : g_iKH);
        uint32_t dst = uKV + (uint32_t)(isV*7680 + isL*3840) + (uint32_t)r*80 + (uint32_t)q*16;
        cpa16(dst, src + base + r*32 + q*8);
    }
    CPA_COMMIT();
    __syncthreads();

    uint32_t aQoff = (uint32_t)(wid*16 + (lane & 7) + ((lane >> 3) & 1)*8)*80
                   + ((lane >> 4) & 1)*16;
    uint32_t qH[2][4], qL[2][4];
#pragma unroll
    for (int ks = 0; ks < 2; ks++) {
        ldsm4(qH[ks][0], qH[ks][1], qH[ks][2], qH[ks][3], uQH + aQoff + ks*32);
        ldsm4(qL[ks][0], qL[ks][1], qL[ks][2], qL[ks][3], uQL + aQoff + ks*32);
    }

    float o[4][4];
#pragma unroll
    for (int j = 0; j < 4; j++)
#pragma unroll
        for (int q = 0; q < 4; q++) o[j][q] = 0.f;
    float m0 = -1e30f, m1 = -1e30f, sum0 = 0.f, sum1 = 0.f;

    uint32_t kOff = (uint32_t)((lane & 7) + ((lane >> 4) & 1)*8)*80 + ((lane >> 3) & 1)*16;
    uint32_t vOffT = (uint32_t)((lane & 7) + ((lane >> 3) & 1)*8)*80 + ((lane >> 4) & 1)*16;

    for (int kt = 0; kt < 7; kt++) {
        CPA_WAIT0();
        __syncthreads();
        if (kt < 6) {
            int kb0 = (kt + 1)*KT;
            uint32_t bufn = uKV + (uint32_t)(((kt + 1) & 1))*15360;
#pragma unroll
            for (int i = 0; i < 3; i++) {
                int f = tid + 256*i;
                int isL = f >= 384; int g2 = isL ? f - 384 : f;
                int isV = g2 >= 192; int e = isV ? g2 - 192 : g2;
                int r = e >> 2, q = e & 3;
                const __nv_bfloat16* src = isV ? (isL ? g_iVL : g_iVH)
                                               : (isL ? g_iKL : g_iKH);
                uint32_t dst = bufn + (uint32_t)(isV*7680 + isL*3840)
                             + (uint32_t)r*80 + (uint32_t)q*16;
                cpa16(dst, src + base + (kb0 + r)*32 + q*8);
            }
            CPA_COMMIT();
        }
        uint32_t kvb = uKV + (uint32_t)(kt & 1)*15360;
        uint32_t uKHb = kvb, uKLb = kvb + 3840;
        uint32_t uVHb = kvb + 7680, uVLb = kvb + 11520;

        // scores S (16 x 48) = Q K^T, 3-term bf16 split
        float sc[6][4];
#pragma unroll
        for (int j = 0; j < 6; j++)
#pragma unroll
            for (int q = 0; q < 4; q++) sc[j][q] = 0.f;
#pragma unroll
        for (int ks = 0; ks < 2; ks++) {
#pragma unroll
            for (int ng = 0; ng < 3; ng++) {
                uint32_t bH[4], bL[4];
                ldsm4(bH[0], bH[1], bH[2], bH[3], uKHb + kOff + ng*(16*80) + ks*32);
                ldsm4(bL[0], bL[1], bL[2], bL[3], uKLb + kOff + ng*(16*80) + ks*32);
                mma16816(sc[2*ng],   qH[ks], &bH[0]);
                mma16816(sc[2*ng+1], qH[ks], &bH[2]);
                mma16816(sc[2*ng],   qH[ks], &bL[0]);
                mma16816(sc[2*ng+1], qH[ks], &bL[2]);
                mma16816(sc[2*ng],   qL[ks], &bH[0]);
                mma16816(sc[2*ng+1], qL[ks], &bH[2]);
            }
        }

        // online softmax
        float t0 = -1e30f, t1 = -1e30f;
#pragma unroll
        for (int j = 0; j < 6; j++) {
            t0 = fmaxf(t0, fmaxf(sc[j][0], sc[j][1]));
            t1 = fmaxf(t1, fmaxf(sc[j][2], sc[j][3]));
        }
        t0 = fmaxf(t0, __shfl_xor_sync(0xffffffffu, t0, 1));
        t0 = fmaxf(t0, __shfl_xor_sync(0xffffffffu, t0, 2));
        t1 = fmaxf(t1, __shfl_xor_sync(0xffffffffu, t1, 1));
        t1 = fmaxf(t1, __shfl_xor_sync(0xffffffffu, t1, 2));
        float nm0 = fmaxf(m0, t0), nm1 = fmaxf(m1, t1);
        float c0 = __expf(m0 - nm0), c1 = __expf(m1 - nm1);
        float ts0 = 0.f, ts1 = 0.f;
#pragma unroll
        for (int j = 0; j < 6; j++) {
            sc[j][0] = __expf(sc[j][0] - nm0);
            sc[j][1] = __expf(sc[j][1] - nm0);
            sc[j][2] = __expf(sc[j][2] - nm1);
            sc[j][3] = __expf(sc[j][3] - nm1);
            ts0 += sc[j][0] + sc[j][1];
            ts1 += sc[j][2] + sc[j][3];
        }
        sum0 = sum0*c0 + ts0;
        sum1 = sum1*c1 + ts1;
#pragma unroll
        for (int j = 0; j < 4; j++) {
            o[j][0] *= c0; o[j][1] *= c0; o[j][2] *= c1; o[j][3] *= c1;
        }
        m0 = nm0; m1 = nm1;

        // PV, 3-term split (V via ldsm.trans on [key][d])
#pragma unroll
        for (int kb = 0; kb < 3; kb++) {
            uint32_t aP[4], aR[4];
#pragma unroll
            for (int t = 0; t < 2; t++) {
                int j = 2*kb + t;
                float x0 = sc[j][0], x1 = sc[j][1], x2 = sc[j][2], x3 = sc[j][3];
                __nv_bfloat162 h01 = __floats2bfloat162_rn(x0, x1);
                __nv_bfloat162 h23 = __floats2bfloat162_rn(x2, x3);
                aP[2*t]   = *(uint32_t*)&h01;
                aP[2*t+1] = *(uint32_t*)&h23;
                aR[2*t]   = pk_bf2(x0 - __bfloat162float(h01.x),
                                   x1 - __bfloat162float(h01.y));
                aR[2*t+1] = pk_bf2(x2 - __bfloat162float(h23.x),
                                   x3 - __bfloat162float(h23.y));
            }
#pragma unroll
            for (int ng = 0; ng < 2; ng++) {
                uint32_t vH[4], vL[4];
                ldsm4t(vH[0], vH[1], vH[2], vH[3], uVHb + vOffT + kb*1280 + ng*32);
                ldsm4t(vL[0], vL[1], vL[2], vL[3], uVLb + vOffT + kb*1280 + ng*32);
                mma16816(o[2*ng],   aP, &vH[0]);
                mma16816(o[2*ng+1], aP, &vH[2]);
                mma16816(o[2*ng],   aP, &vL[0]);
                mma16816(o[2*ng+1], aP, &vL[2]);
                mma16816(o[2*ng],   aR, &vH[0]);
                mma16816(o[2*ng+1], aR, &vH[2]);
            }
        }
    }

    // finalize
    sum0 += __shfl_xor_sync(0xffffffffu, sum0, 1);
    sum0 += __shfl_xor_sync(0xffffffffu, sum0, 2);
    sum1 += __shfl_xor_sync(0xffffffffu, sum1, 1);
    sum1 += __shfl_xor_sync(0xffffffffu, sum1, 2);
    float inv0 = 1.f / sum0, inv1 = 1.f / sum1;
    int q0 = qb + wid*16 + (lane >> 2);
    int q1 = q0 + 8;
    int cbase = h*32 + 2*(lane & 3);
#pragma unroll
    for (int j = 0; j < 4; j++) {
        int col = cbase + 8*j;
        if (q0 < 336) {
            float2 w0; w0.x = o[j][0]*inv0; w0.y = o[j][1]*inv0;
            *(float2*)&g_O[(g*SS + q0)*DD + col] = w0;
        }
        if (q1 < 336) {
            float2 w1; w1.x = o[j][2]*inv1; w1.y = o[j][3]*inv1;
            *(float2*)&g_O[(g*SS + q1)*DD + col] = w1;
        }
    }
}

// ---------------- variable attention (L=8, fp32 path) ----------------
__global__ void __launch_bounds__(64) k_attn_var() {
    __shared__ __align__(16) float Ks[8][256];
    __shared__ __align__(16) float Vs[8][256];

    int bs = blockIdx.x;
    int b = bs / SS;
    int s = bs - b*SS;
    int tid = threadIdx.x;

#pragma unroll
    for (int i = 0; i < 8; i++) {
        int f = tid + 64*i;
        int v = f >> 6;
        int dq = f & 63;
        int ga = ((b*VV + v)*SS + s)*DD + dq*4;
        *(float4*)&Ks[v][dq*4] = *(const float4*)&g_K[ga];
        *(float4*)&Vs[v][dq*4] = *(const float4*)&g_V[ga];
    }
    __syncthreads();

    int qv = tid & 7;
    int h  = tid >> 3;
    const float* qp = &g_Q[((b*VV + qv)*SS + s)*DD + h*32];
    float q[32];
#pragma unroll
    for (int i = 0; i < 8; i++) {
        float4 v4 = *(const float4*)&qp[i*4];
        q[i*4+0] = v4.x; q[i*4+1] = v4.y; q[i*4+2] = v4.z; q[i*4+3] = v4.w;
    }
    float sc[8];
    float mx = -1e30f;
#pragma unroll
    for (int v = 0; v < 8; v++) {
        float t = 0.f;
#pragma unroll
        for (int d = 0; d < 32; d++) t += q[d]*Ks[v][h*32 + d];
        t *= RSQRT_DK;
        sc[v] = t;
        mx = fmaxf(mx, t);
    }
    float sum = 0.f;
#pragma unroll
    for (int v = 0; v < 8; v++) { sc[v] = __expf(sc[v] - mx); sum += sc[v]; }
    float inv = 1.f / sum;

    float o[32];
#pragma unroll
    for (int d = 0; d < 32; d++) o[d] = 0.f;
#pragma unroll
    for (int v = 0; v < 8; v++)
#pragma unroll
        for (int d = 0; d < 32; d++) o[d] += sc[v]*Vs[v][h*32 + d];

    float* op = &g_O[((b*VV + qv)*SS + s)*DD + h*32];
#pragma unroll
    for (int i = 0; i < 8; i++) {
        float4 v4;
        v4.x = o[i*4+0]*inv; v4.y = o[i*4+1]*inv;
        v4.z = o[i*4+2]*inv; v4.w = o[i*4+3]*inv;
        *(float4*)&op[i*4] = v4;
    }
}

// ---------------- final projection ----------------
__global__ void k_out_init(const float* __restrict__ pb, float* __restrict__ out) {
    int i = blockIdx.x*256 + threadIdx.x;
    if (i < BB*PP*VV) {
        int p = (i % (PP*VV)) >> 3;
        out[i] = pb[p];
    }
}

__global__ void __launch_bounds__(256) k_proj(const float* __restrict__ W,
                                              float* __restrict__ out) {
    __shared__ float Ws[64][96];
    __shared__ float Es[16][64];
    int k0 = blockIdx.x * 512;
    int tid = threadIdx.x;

    float acc[6];
    const float* erow[6];
    int wcol[6], oidx[6];
#pragma unroll
    for (int i = 0; i < 6; i++) {
        int qq = tid + 256*i;
        int bv = qq / 96;
        int p  = qq - bv*96;
        acc[i] = 0.f;
        erow[i] = &Es[bv][0];
        wcol[i] = p;
        oidx[i] = (bv >> 3)*(PP*VV) + p*VV + (bv & 7);
    }

    for (int kt = 0; kt < 8; kt++) {
        int kb = k0 + kt*64;
        __syncthreads();
#pragma unroll
        for (int i = 0; i < 6; i++) {
            int f = tid + 256*i;
            int kk = f / 24;
            int pq = f - kk*24;
            *(float4*)&Ws[kk][pq*4] = *(const float4*)&W[(kb + kk)*PP + pq*4];
        }
        {
            int bv = tid >> 4;
            int kq = tid & 15;
            *(float4*)&Es[bv][kq*4] = *(const float4*)&g_E[bv*SD + kb + kq*4];
        }
        __syncthreads();
        for (int kk = 0; kk < 64; kk++) {
#pragma unroll
            for (int i = 0; i < 6; i++)
                acc[i] += erow[i][kk] * Ws[kk][wcol[i]];
        }
    }
#pragma unroll
    for (int i = 0; i < 6; i++)
        atomicAdd(&out[oidx[i]], acc[i]);
}

// ---------------- launch ----------------
extern "C" void kernel_launch(void* const* d_in, const int* in_sizes, int n_in,
                              void* d_out, int out_size) {
    const float* x      = (const float*)d_in[0];
    const float* emb_w  = (const float*)d_in[1];
    const float* emb_b  = (const float*)d_in[2];
    const float* Wq     = (const float*)d_in[3];
    const float* bq     = (const float*)d_in[4];
    const float* Wk     = (const float*)d_in[5];
    const float* bk     = (const float*)d_in[6];
    const float* Wv     = (const float*)d_in[7];
    const float* bv     = (const float*)d_in[8];
    const float* Wo     = (const float*)d_in[9];
    const float* bo     = (const float*)d_in[10];
    const float* ln1_g  = (const float*)d_in[11];
    const float* ln1_b  = (const float*)d_in[12];
    const float* norm_g = (const float*)d_in[13];
    const float* norm_b = (const float*)d_in[14];
    const float* proj_w = (const float*)d_in[15];
    const float* proj_b = (const float*)d_in[16];
    float* out = (float*)d_out;

    cudaFuncSetAttribute(k_tgemm_qkv_img, cudaFuncAttributeMaxDynamicSharedMemorySize, SMEM_T(128));
    cudaFuncSetAttribute(k_tgemm_qkv_f32, cudaFuncAttributeMaxDynamicSharedMemorySize, SMEM_T(128));
    cudaFuncSetAttribute(k_wo,            cudaFuncAttributeMaxDynamicSharedMemorySize, SMEM_WO);
    cudaFuncSetAttribute(k_attn_time,     cudaFuncAttributeMaxDynamicSharedMemorySize, ATT_SMEM);

    k_prep<<<dim3(256, 4), 256>>>(Wq, Wk, Wv, Wo);
    k_embed<<<NT, 256>>>(x, emb_w, emb_b);

    for (int it = 0; it < 10; it++) {
        // phase A: attention over time axis (bf16 image path)
        k_tgemm_qkv_img<<<dim3(42, 3), 512, SMEM_T(128)>>>(bq, bk, bv);
        k_attn_time<<<dim3(3, 8, 16), 256, ATT_SMEM>>>();
        k_wo<<<84, 256, SMEM_WO>>>(bo, ln1_g, ln1_b, norm_g, norm_b, 1);
        // phase B: attention over variable axis (fp32 path)
        k_tgemm_qkv_f32<<<dim3(42, 3), 512, SMEM_T(128)>>>(bq, bk, bv);
        k_attn_var<<<BB*SS, 64>>>();
        k_wo<<<84, 256, SMEM_WO>>>(bo, ln1_g, ln1_b, norm_g, norm_b, 0);
    }

    k_out_init<<<6, 256>>>(proj_b, out);
    k_proj<<<SD/512, 256>>>(proj_w, out);
}